// round 4
// baseline (speedup 1.0000x reference)
#include <cuda_runtime.h>
#include <stdint.h>
#include <math.h>

// Problem constants
#define Tn    2048
#define EMB   128
#define NH    8
#define Mv    9      // M
#define Pp    36     // P
#define BT    4096   // B*T
#define D1    1024   // NH*EMB
#define D3    3072   // 3*D1
#define WMAX  42     // max staged window rows (dil<3 -> ext<=13 -> 16+2*13 = 42)

// Scratch (static device arrays; no allocation allowed)
__device__ float g_qkv[BT * D3];      // rows: [Q(1024) | K(1024) | V(1024)]
__device__ float g_attnout[BT * D1];
__device__ int   g_idx[BT * Pp];
__device__ float g_w[BT * Pp];
__device__ float g_part[8][BT * 128]; // split-K partials for out gemm

// ---------------- threefry-2x32 (JAX-compatible, 20 rounds) ----------------
__device__ __forceinline__ void tf2x32(uint32_t k0, uint32_t k1,
                                       uint32_t& x0, uint32_t& x1) {
  uint32_t ks2 = k0 ^ k1 ^ 0x1BD11BDAu;
  x0 += k0; x1 += k1;
#define TFR(r) { x0 += x1; x1 = (x1 << (r)) | (x1 >> (32 - (r))); x1 ^= x0; }
  TFR(13) TFR(15) TFR(26) TFR(6)
  x0 += k1;  x1 += ks2 + 1u;
  TFR(17) TFR(29) TFR(16) TFR(24)
  x0 += ks2; x1 += k0 + 2u;
  TFR(13) TFR(15) TFR(26) TFR(6)
  x0 += k0;  x1 += k1 + 3u;
  TFR(17) TFR(29) TFR(16) TFR(24)
  x0 += k1;  x1 += ks2 + 4u;
  TFR(13) TFR(15) TFR(26) TFR(6)
  x0 += ks2; x1 += k0 + 5u;
#undef TFR
}

// ---------------- Kernel 1: fused QKV projection GEMM ----------------------
// C(4096 x 3072) = X(4096 x 128) @ [Wq | Wk | Wv], Q/K scaled by 1/128^0.25
// 128x128 tile / 256 threads, 8x8 per thread, BK=32.
__global__ __launch_bounds__(256, 2) void qkv_gemm(const float* __restrict__ X,
                                                   const float* __restrict__ Wq,
                                                   const float* __restrict__ Wk,
                                                   const float* __restrict__ Wv) {
  __shared__ float As[128][36];   // [m][k] padded (float4-aligned)
  __shared__ float Bs[32][128];   // [k][n]
  int bm = blockIdx.y, bn = blockIdx.x;
  int cstart = bn * 128;
  int seg = cstart >> 10;
  const float* W = (seg == 0) ? Wq : ((seg == 1) ? Wk : Wv);
  int ccol = cstart & 1023;
  float scale = (seg < 2) ? 0.29730177875068026f : 1.0f; // 1/128^0.25
  int tid = threadIdx.x;
  int ty = tid >> 4, tx = tid & 15;
  float acc[8][8] = {};
  for (int kc = 0; kc < 128; kc += 32) {
    // X tile 128x32: 1024 float4
#pragma unroll
    for (int it = 0; it < 4; it++) {
      int lin = tid + it * 256;
      int r = lin >> 3, c4 = lin & 7;
      float4 v = *(const float4*)(X + (size_t)(bm * 128 + r) * 128 + kc + c4 * 4);
      *(float4*)&As[r][c4 * 4] = v;
    }
    // W tile 32x128: 1024 float4
#pragma unroll
    for (int it = 0; it < 4; it++) {
      int lin = tid + it * 256;
      int k = lin >> 5, c4 = lin & 31;
      float4 v = *(const float4*)(W + (size_t)(kc + k) * 1024 + ccol + c4 * 4);
      *(float4*)&Bs[k][c4 * 4] = v;
    }
    __syncthreads();
#pragma unroll
    for (int k = 0; k < 32; k++) {
      float a[8];
#pragma unroll
      for (int i = 0; i < 8; i++) a[i] = As[ty * 8 + i][k];
      float4 b0 = *(const float4*)&Bs[k][tx * 8];
      float4 b1 = *(const float4*)&Bs[k][tx * 8 + 4];
#pragma unroll
      for (int i = 0; i < 8; i++) {
        acc[i][0] += a[i] * b0.x; acc[i][1] += a[i] * b0.y;
        acc[i][2] += a[i] * b0.z; acc[i][3] += a[i] * b0.w;
        acc[i][4] += a[i] * b1.x; acc[i][5] += a[i] * b1.y;
        acc[i][6] += a[i] * b1.z; acc[i][7] += a[i] * b1.w;
      }
    }
    __syncthreads();
  }
#pragma unroll
  for (int i = 0; i < 8; i++) {
    float* dst = g_qkv + (size_t)(bm * 128 + ty * 8 + i) * D3 + cstart + tx * 8;
    float4 o0 = make_float4(acc[i][0] * scale, acc[i][1] * scale,
                            acc[i][2] * scale, acc[i][3] * scale);
    float4 o1 = make_float4(acc[i][4] * scale, acc[i][5] * scale,
                            acc[i][6] * scale, acc[i][7] * scale);
    *(float4*)dst = o0;
    *(float4*)(dst + 4) = o1;
  }
}

// ---------------- Kernel 2: indices + weights per token --------------------
__global__ __launch_bounds__(64) void idxw_kernel(const float* __restrict__ sp,
                                                  const float* __restrict__ mvals) {
  int token = blockIdx.x;            // 0..4095
  int b = token >> 11, t = token & 2047;
  int p = threadIdx.x;
  __shared__ float s_mean[Mv];
  __shared__ float s_sigma_inv;
  __shared__ int   s_idx[Pp];
  __shared__ float s_ptsfl[Pp];
  __shared__ float s_dens[Pp][Mv];
  __shared__ float s_colinv[Mv];

  float dil = sp[0];
  if (p < Mv) {
    // exact mul+add (no FMA contraction) to match JAX rounding
    float off = __fmul_rn((float)(p - 4), dil);
    float mu  = __fadd_rn((float)t, off);
    mu = fminf(fmaxf(mu, 0.0f), (float)(Tn - 1));
    s_mean[p] = mu;
  }
  if (p == 0) {
    float s = sp[1] + 2.0f;                 // SIGMA_BOOST
    float sigma = log1pf(expf(s)) + 1e-7f;  // softplus + EPS
    s_sigma_inv = 1.0f / sigma;
  }
  __syncthreads();

  if (p < Pp) {
    int m = p >> 2, slot = p & 3;
    float fl = floorf(s_mean[m]);
    float val;
    if (slot == 0) val = fl;
    else if (slot == 1) val = fl + 1.0f;
    else {
      // JAX partitionable threefry:
      //   split(key(42))[1] = threefry2x32((0,42), (0,1))  [both words]
      //   random_bits elem i: (b1,b2)=threefry2x32(k2,(0,i)); bits=b1^b2
      //   randint span 2048 (pow2) -> bits & 2047
      uint32_t k2a = 0u, k2b = 1u;
      tf2x32(0u, 42u, k2a, k2b);
      uint32_t i = (uint32_t)(b * 36864 + t * 18 + m * 2 + (slot - 2));
      uint32_t x0 = 0u, x1 = i;
      tf2x32(k2a, k2b, x0, x1);
      uint32_t bits = x0 ^ x1;
      val = (float)(bits & 2047u);
    }
    val = fminf(fmaxf(val, 0.0f), (float)(Tn - 1));
    int iv = (int)val;
    s_idx[p] = iv;
    s_ptsfl[p] = (float)iv;
  }
  __syncthreads();

  if (p < Pp) {
    bool dup = false;
    int my = s_idx[p];
    for (int q = 0; q < p; q++) dup |= (s_idx[q] == my);
    float inv_s = s_sigma_inv;
#pragma unroll
    for (int m = 0; m < Mv; m++) {
      float d = (s_ptsfl[p] - s_mean[m]) * inv_s;
      s_dens[p][m] = dup ? 0.0f : expf(-0.5f * d * d);
    }
  }
  __syncthreads();

  if (p < Mv) {
    float sum = 0.0f;
    for (int q = 0; q < Pp; q++) sum += s_dens[q][p];
    s_colinv[p] = 1.0f / sum;
  }
  __syncthreads();

  if (p < Pp) {
    float w = 0.0f;
#pragma unroll
    for (int m = 0; m < Mv; m++) w += s_dens[p][m] * s_colinv[m] * mvals[m];
    g_idx[token * Pp + p] = s_idx[p];
    g_w[token * Pp + p] = w;
  }
}

// ---------------- Kernel 3: gathered attention ------------------------------
// CTA = 16 consecutive tokens x 1 head. The 20 local points per token provably
// fall in [t0-ext, t0+15+ext] (ext = int(4*dil)+1 <= 13) -> stage that K/V
// window in smem with one coalesced load; only global points gather from L2.
__global__ __launch_bounds__(512) void attn_kernel(const float* __restrict__ sp) {
  __shared__ float sK[WMAX * 128];
  __shared__ float sV[WMAX * 128];
  __shared__ float s_logit[16][Pp];
  int tid = threadIdx.x;
  int wid = tid >> 5;
  int lane = tid & 31;
  int h = blockIdx.y;
  int tokblk = blockIdx.x * 16;
  int b = tokblk >> 11;
  int t0 = tokblk & 2047;

  float dil = sp[0];
  int ext = (int)(4.0f * dil) + 1;
  int lo = max(t0 - ext, 0);
  int hi = min(t0 + 15 + ext, Tn - 1);
  int nrows = hi - lo + 1;

  size_t rowbase = (size_t)(b * Tn) * D3;
  // stage K and V window (coalesced)
  for (int i = tid; i < nrows * 32; i += 512) {
    int r = i >> 5, c4 = i & 31;
    size_t src = rowbase + (size_t)(lo + r) * D3 + h * EMB + c4 * 4;
    *(float4*)&sK[r * 128 + c4 * 4] = *(const float4*)(g_qkv + src + D1);
    *(float4*)&sV[r * 128 + c4 * 4] = *(const float4*)(g_qkv + src + 2 * D1);
  }
  __syncthreads();

  int token = tokblk + wid;
  float4 q = *(const float4*)(g_qkv + (size_t)token * D3 + h * EMB + lane * 4);

  const int* ip = g_idx + token * Pp;
  const float* wp = g_w + token * Pp;
  int   idxA = ip[lane];
  float wA   = wp[lane];
  int   idxB = (lane < 4) ? ip[32 + lane] : 0;
  float wB   = (lane < 4) ? wp[32 + lane] : 0.0f;

  for (int p = 0; p < Pp; p++) {
    int   j = (p < 32) ? __shfl_sync(0xffffffffu, idxA, p)
                       : __shfl_sync(0xffffffffu, idxB, p - 32);
    float w = (p < 32) ? __shfl_sync(0xffffffffu, wA, p)
                       : __shfl_sync(0xffffffffu, wB, p - 32);
    const float* ksrc = (j >= lo && j <= hi)
        ? &sK[(j - lo) * 128 + lane * 4]
        : (g_qkv + rowbase + (size_t)j * D3 + D1 + h * EMB + lane * 4);
    float4 k4 = *(const float4*)ksrc;
    float d = q.x * k4.x + q.y * k4.y + q.z * k4.z + q.w * k4.w;
    d += __shfl_xor_sync(0xffffffffu, d, 16);
    d += __shfl_xor_sync(0xffffffffu, d, 8);
    d += __shfl_xor_sync(0xffffffffu, d, 4);
    d += __shfl_xor_sync(0xffffffffu, d, 2);
    d += __shfl_xor_sync(0xffffffffu, d, 1);
    if (lane == 0) s_logit[wid][p] = w * d;
  }
  __syncwarp();

  float mx = -1e30f;
#pragma unroll
  for (int p = 0; p < Pp; p++) mx = fmaxf(mx, s_logit[wid][p]);

  float4 acc = make_float4(0.f, 0.f, 0.f, 0.f);
  float sum = 0.0f;
  for (int p = 0; p < Pp; p++) {
    float a = __expf(s_logit[wid][p] - mx);
    sum += a;
    int j = (p < 32) ? __shfl_sync(0xffffffffu, idxA, p)
                     : __shfl_sync(0xffffffffu, idxB, p - 32);
    const float* vsrc = (j >= lo && j <= hi)
        ? &sV[(j - lo) * 128 + lane * 4]
        : (g_qkv + rowbase + (size_t)j * D3 + 2 * D1 + h * EMB + lane * 4);
    float4 v4 = *(const float4*)vsrc;
    acc.x += a * v4.x; acc.y += a * v4.y; acc.z += a * v4.z; acc.w += a * v4.w;
  }
  float inv = 1.0f / sum;
  float4 o = make_float4(acc.x * inv, acc.y * inv, acc.z * inv, acc.w * inv);
  *(float4*)(g_attnout + (size_t)token * D1 + h * EMB + lane * 4) = o;
}

// ---------------- Kernel 4: output GEMM (split-K x8) -------------------------
// partial[ks](4096 x 128) = attnout(4096 x [ks*128..+128)) @ Wu-slice
// 128x128 tile / 256 threads, 8x8 per thread, BK=32.
__global__ __launch_bounds__(256, 2) void out_gemm_split(const float* __restrict__ Wu) {
  __shared__ float As[128][36];
  __shared__ float Bs[32][128];
  int bm = blockIdx.x, ks = blockIdx.y;
  int tid = threadIdx.x;
  int ty = tid >> 4, tx = tid & 15;
  float acc[8][8] = {};
  int kbase = ks * 128;
  for (int kc = kbase; kc < kbase + 128; kc += 32) {
#pragma unroll
    for (int it = 0; it < 4; it++) {
      int lin = tid + it * 256;
      int r = lin >> 3, c4 = lin & 7;
      float4 v = *(const float4*)(g_attnout + (size_t)(bm * 128 + r) * 1024 + kc + c4 * 4);
      *(float4*)&As[r][c4 * 4] = v;
    }
#pragma unroll
    for (int it = 0; it < 4; it++) {
      int lin = tid + it * 256;
      int k = lin >> 5, c4 = lin & 31;
      float4 v = *(const float4*)(Wu + (size_t)(kc + k) * 128 + c4 * 4);
      *(float4*)&Bs[k][c4 * 4] = v;
    }
    __syncthreads();
#pragma unroll
    for (int k = 0; k < 32; k++) {
      float a[8];
#pragma unroll
      for (int i = 0; i < 8; i++) a[i] = As[ty * 8 + i][k];
      float4 b0 = *(const float4*)&Bs[k][tx * 8];
      float4 b1 = *(const float4*)&Bs[k][tx * 8 + 4];
#pragma unroll
      for (int i = 0; i < 8; i++) {
        acc[i][0] += a[i] * b0.x; acc[i][1] += a[i] * b0.y;
        acc[i][2] += a[i] * b0.z; acc[i][3] += a[i] * b0.w;
        acc[i][4] += a[i] * b1.x; acc[i][5] += a[i] * b1.y;
        acc[i][6] += a[i] * b1.z; acc[i][7] += a[i] * b1.w;
      }
    }
    __syncthreads();
  }
  float* dst0 = g_part[ks];
#pragma unroll
  for (int i = 0; i < 8; i++) {
    float* dst = dst0 + (size_t)(bm * 128 + ty * 8 + i) * 128 + tx * 8;
    *(float4*)dst       = make_float4(acc[i][0], acc[i][1], acc[i][2], acc[i][3]);
    *(float4*)(dst + 4) = make_float4(acc[i][4], acc[i][5], acc[i][6], acc[i][7]);
  }
}

// Deterministic reduce of the 8 split-K partials + bias.
__global__ __launch_bounds__(256) void out_reduce(float* __restrict__ Cout,
                                                  const float* __restrict__ bu) {
  int e4 = blockIdx.x * 256 + threadIdx.x;   // float4 index, 0..131071
  int col0 = (e4 * 4) & 127;
  float4 s = *(const float4*)(bu + col0);
#pragma unroll
  for (int ks = 0; ks < 8; ks++) {
    float4 p = *(const float4*)(g_part[ks] + e4 * 4);
    s.x += p.x; s.y += p.y; s.z += p.z; s.w += p.w;
  }
  *(float4*)(Cout + e4 * 4) = s;
}

// ---------------- launch ----------------------------------------------------
extern "C" void kernel_launch(void* const* d_in, const int* in_sizes, int n_in,
                              void* d_out, int out_size) {
  const float* x   = (const float*)d_in[0];
  const float* sp  = (const float*)d_in[1];
  const float* mv  = (const float*)d_in[2];
  const float* Wq  = (const float*)d_in[3];
  const float* Wk  = (const float*)d_in[4];
  const float* Wv  = (const float*)d_in[5];
  const float* Wu  = (const float*)d_in[6];
  const float* bu  = (const float*)d_in[7];
  float* out = (float*)d_out;

  qkv_gemm<<<dim3(24, 32), 256>>>(x, Wq, Wk, Wv);
  idxw_kernel<<<BT, 64>>>(sp, mv);
  attn_kernel<<<dim3(256, 8), 512>>>(sp);
  out_gemm_split<<<dim3(32, 8), 256>>>(Wu);
  out_reduce<<<512, 256>>>(out, bu);
}

// round 5
// speedup vs baseline: 1.2180x; 1.2180x over previous
#include <cuda_runtime.h>
#include <cuda_bf16.h>
#include <stdint.h>
#include <math.h>

// Problem constants
#define Tn    2048
#define EMB   128
#define NH    8
#define Mv    9      // M
#define Pp    36     // P
#define BT    4096   // B*T
#define D1    1024   // NH*EMB
#define D3    3072   // 3*D1

// Scratch (static device arrays; no allocation allowed)
__device__ float g_qkv[BT * D3];      // rows: [Q(1024) | K(1024) | V(1024)]
__device__ float g_attnout[BT * D1];
__device__ int   g_idx[BT * Pp];
__device__ float g_w[BT * Pp];
__device__ float g_part[4][BT * 128]; // split-K partials for out gemm

// ---------------- threefry-2x32 (JAX-compatible, 20 rounds) ----------------
__device__ __forceinline__ void tf2x32(uint32_t k0, uint32_t k1,
                                       uint32_t& x0, uint32_t& x1) {
  uint32_t ks2 = k0 ^ k1 ^ 0x1BD11BDAu;
  x0 += k0; x1 += k1;
#define TFR(r) { x0 += x1; x1 = (x1 << (r)) | (x1 >> (32 - (r))); x1 ^= x0; }
  TFR(13) TFR(15) TFR(26) TFR(6)
  x0 += k1;  x1 += ks2 + 1u;
  TFR(17) TFR(29) TFR(16) TFR(24)
  x0 += ks2; x1 += k0 + 2u;
  TFR(13) TFR(15) TFR(26) TFR(6)
  x0 += k0;  x1 += k1 + 3u;
  TFR(17) TFR(29) TFR(16) TFR(24)
  x0 += k1;  x1 += ks2 + 4u;
  TFR(13) TFR(15) TFR(26) TFR(6)
  x0 += ks2; x1 += k0 + 5u;
#undef TFR
}

// ---------------- bf16 MMA helpers -----------------------------------------
__device__ __forceinline__ void mma16816(float* c, const uint32_t* a, const uint32_t* b) {
  asm volatile(
    "mma.sync.aligned.m16n8k16.row.col.f32.bf16.bf16.f32 "
    "{%0,%1,%2,%3}, {%4,%5,%6,%7}, {%8,%9}, {%0,%1,%2,%3};"
    : "+f"(c[0]), "+f"(c[1]), "+f"(c[2]), "+f"(c[3])
    : "r"(a[0]), "r"(a[1]), "r"(a[2]), "r"(a[3]), "r"(b[0]), "r"(b[1]));
}

__device__ __forceinline__ void split_bf16(float x, __nv_bfloat16& h, __nv_bfloat16& l) {
  h = __float2bfloat16(x);
  l = __float2bfloat16(x - __bfloat162float(h));
}

// smem tile strides (bf16 elements)
#define XPAD 40   // A rows: 32 k + 8 pad -> conflict-free frag loads
#define WPAD 36   // B rows (transposed [n][k]): 32 k + 4 pad

// ---------------- Kernel 1: fused QKV projection (tensor core) -------------
// C(4096 x 3072) = X(4096 x 128) @ [Wq|Wk|Wv]; Q/K scaled by 1/128^0.25.
// Block 128x64, 8 warps (warp tile 32x32), bf16x3 split, fp32 accumulate.
__global__ __launch_bounds__(256, 2) void qkv_gemm(const float* __restrict__ X,
                                                   const float* __restrict__ Wq,
                                                   const float* __restrict__ Wk,
                                                   const float* __restrict__ Wv) {
  __shared__ __nv_bfloat16 sXh[128 * XPAD], sXl[128 * XPAD];
  __shared__ __nv_bfloat16 sWh[64 * WPAD],  sWl[64 * WPAD];
  int bn = blockIdx.x, bm = blockIdx.y;
  int cstart = bn * 64;
  int seg = cstart >> 10;
  const float* W = (seg == 0) ? Wq : ((seg == 1) ? Wk : Wv);
  int ccol = cstart & 1023;
  float scale = (seg < 2) ? 0.29730177875068026f : 1.0f;
  int tid = threadIdx.x;
  int wid = tid >> 5, lane = tid & 31;
  int wm = wid >> 1, wn = wid & 1;
  int g = lane >> 2, t = lane & 3;

  float acc[2][4][4] = {};

  for (int kc = 0; kc < 128; kc += 32) {
    // load + split X tile 128x32 (1024 float4)
#pragma unroll
    for (int it = 0; it < 4; it++) {
      int idx = tid + it * 256;
      int r = idx >> 3, c4 = idx & 7;
      float4 v = *(const float4*)(X + (size_t)(bm * 128 + r) * 128 + kc + c4 * 4);
      int o = r * XPAD + c4 * 4;
      split_bf16(v.x, sXh[o + 0], sXl[o + 0]);
      split_bf16(v.y, sXh[o + 1], sXl[o + 1]);
      split_bf16(v.z, sXh[o + 2], sXl[o + 2]);
      split_bf16(v.w, sXh[o + 3], sXl[o + 3]);
    }
    // load + split W tile 32x64, stored transposed [n][k]
#pragma unroll
    for (int it = 0; it < 2; it++) {
      int idx = tid + it * 256;
      int k = idx >> 4, c4 = idx & 15;
      float4 v = *(const float4*)(W + (size_t)(kc + k) * 1024 + ccol + c4 * 4);
      float vv[4] = {v.x, v.y, v.z, v.w};
#pragma unroll
      for (int j = 0; j < 4; j++) {
        int n = c4 * 4 + j;
        split_bf16(vv[j], sWh[n * WPAD + k], sWl[n * WPAD + k]);
      }
    }
    __syncthreads();

#pragma unroll
    for (int ks = 0; ks < 32; ks += 16) {
      uint32_t Ah[2][4], Al[2][4], Bh[4][2], Bl[4][2];
#pragma unroll
      for (int mt = 0; mt < 2; mt++) {
        int r0 = (wm * 32 + mt * 16 + g) * XPAD + ks + 2 * t;
        Ah[mt][0] = *(const uint32_t*)&sXh[r0];
        Ah[mt][1] = *(const uint32_t*)&sXh[r0 + 8 * XPAD];
        Ah[mt][2] = *(const uint32_t*)&sXh[r0 + 8];
        Ah[mt][3] = *(const uint32_t*)&sXh[r0 + 8 * XPAD + 8];
        Al[mt][0] = *(const uint32_t*)&sXl[r0];
        Al[mt][1] = *(const uint32_t*)&sXl[r0 + 8 * XPAD];
        Al[mt][2] = *(const uint32_t*)&sXl[r0 + 8];
        Al[mt][3] = *(const uint32_t*)&sXl[r0 + 8 * XPAD + 8];
      }
#pragma unroll
      for (int nt = 0; nt < 4; nt++) {
        int n0 = (wn * 32 + nt * 8 + g) * WPAD + ks + 2 * t;
        Bh[nt][0] = *(const uint32_t*)&sWh[n0];
        Bh[nt][1] = *(const uint32_t*)&sWh[n0 + 8];
        Bl[nt][0] = *(const uint32_t*)&sWl[n0];
        Bl[nt][1] = *(const uint32_t*)&sWl[n0 + 8];
      }
#pragma unroll
      for (int mt = 0; mt < 2; mt++)
#pragma unroll
        for (int nt = 0; nt < 4; nt++) {
          mma16816(acc[mt][nt], Ah[mt], Bh[nt]);
          mma16816(acc[mt][nt], Ah[mt], Bl[nt]);
          mma16816(acc[mt][nt], Al[mt], Bh[nt]);
        }
    }
    __syncthreads();
  }

#pragma unroll
  for (int mt = 0; mt < 2; mt++)
#pragma unroll
    for (int nt = 0; nt < 4; nt++) {
      int row = bm * 128 + wm * 32 + mt * 16 + g;
      int col = cstart + wn * 32 + nt * 8 + 2 * t;
      float2 o0 = make_float2(acc[mt][nt][0] * scale, acc[mt][nt][1] * scale);
      float2 o1 = make_float2(acc[mt][nt][2] * scale, acc[mt][nt][3] * scale);
      *(float2*)&g_qkv[(size_t)row * D3 + col] = o0;
      *(float2*)&g_qkv[(size_t)(row + 8) * D3 + col] = o1;
    }
}

// ---------------- Kernel 2: indices + weights per token --------------------
__global__ __launch_bounds__(64) void idxw_kernel(const float* __restrict__ sp,
                                                  const float* __restrict__ mvals) {
  int token = blockIdx.x;            // 0..4095
  int b = token >> 11, t = token & 2047;
  int p = threadIdx.x;
  __shared__ float s_mean[Mv];
  __shared__ float s_sigma_inv;
  __shared__ int   s_idx[Pp];
  __shared__ float s_ptsfl[Pp];
  __shared__ float s_dens[Pp][Mv];
  __shared__ float s_colinv[Mv];

  float dil = sp[0];
  if (p < Mv) {
    float off = __fmul_rn((float)(p - 4), dil);
    float mu  = __fadd_rn((float)t, off);
    mu = fminf(fmaxf(mu, 0.0f), (float)(Tn - 1));
    s_mean[p] = mu;
  }
  if (p == 0) {
    float s = sp[1] + 2.0f;                 // SIGMA_BOOST
    float sigma = log1pf(expf(s)) + 1e-7f;  // softplus + EPS
    s_sigma_inv = 1.0f / sigma;
  }
  __syncthreads();

  if (p < Pp) {
    int m = p >> 2, slot = p & 3;
    float fl = floorf(s_mean[m]);
    float val;
    if (slot == 0) val = fl;
    else if (slot == 1) val = fl + 1.0f;
    else {
      // JAX partitionable threefry (verified in R2)
      uint32_t k2a = 0u, k2b = 1u;
      tf2x32(0u, 42u, k2a, k2b);
      uint32_t i = (uint32_t)(b * 36864 + t * 18 + m * 2 + (slot - 2));
      uint32_t x0 = 0u, x1 = i;
      tf2x32(k2a, k2b, x0, x1);
      uint32_t bits = x0 ^ x1;
      val = (float)(bits & 2047u);
    }
    val = fminf(fmaxf(val, 0.0f), (float)(Tn - 1));
    int iv = (int)val;
    s_idx[p] = iv;
    s_ptsfl[p] = (float)iv;
  }
  __syncthreads();

  if (p < Pp) {
    bool dup = false;
    int my = s_idx[p];
    for (int q = 0; q < p; q++) dup |= (s_idx[q] == my);
    float inv_s = s_sigma_inv;
#pragma unroll
    for (int m = 0; m < Mv; m++) {
      float d = (s_ptsfl[p] - s_mean[m]) * inv_s;
      s_dens[p][m] = dup ? 0.0f : expf(-0.5f * d * d);
    }
  }
  __syncthreads();

  if (p < Mv) {
    float sum = 0.0f;
    for (int q = 0; q < Pp; q++) sum += s_dens[q][p];
    s_colinv[p] = 1.0f / sum;
  }
  __syncthreads();

  if (p < Pp) {
    float w = 0.0f;
#pragma unroll
    for (int m = 0; m < Mv; m++) w += s_dens[p][m] * s_colinv[m] * mvals[m];
    g_idx[token * Pp + p] = s_idx[p];
    g_w[token * Pp + p] = w;
  }
}

// ---------------- Kernel 3: gathered attention (R3 version) ----------------
// CTA = 16 consecutive tokens x 1 head (16 warps); locals hit L1.
__global__ __launch_bounds__(512) void attn_kernel() {
  int wid = threadIdx.x >> 5;
  int lane = threadIdx.x & 31;
  __shared__ float s_logit[16][Pp];
  int token = blockIdx.x * 16 + wid;
  int h = blockIdx.y;
  int b = token >> 11;

  float4 q = *(const float4*)(g_qkv + (size_t)token * D3 + h * EMB + lane * 4);

  const int* ip = g_idx + token * Pp;
  const float* wp = g_w + token * Pp;
  int   idxA = ip[lane];
  float wA   = wp[lane];
  int   idxB = (lane < 4) ? ip[32 + lane] : 0;
  float wB   = (lane < 4) ? wp[32 + lane] : 0.0f;

  size_t rowbase = (size_t)(b * Tn) * D3;

  for (int p = 0; p < Pp; p++) {
    int   j = (p < 32) ? __shfl_sync(0xffffffffu, idxA, p)
                       : __shfl_sync(0xffffffffu, idxB, p - 32);
    float w = (p < 32) ? __shfl_sync(0xffffffffu, wA, p)
                       : __shfl_sync(0xffffffffu, wB, p - 32);
    float4 k4 = *(const float4*)(g_qkv + rowbase + (size_t)j * D3 + D1 + h * EMB + lane * 4);
    float d = q.x * k4.x + q.y * k4.y + q.z * k4.z + q.w * k4.w;
    d += __shfl_xor_sync(0xffffffffu, d, 16);
    d += __shfl_xor_sync(0xffffffffu, d, 8);
    d += __shfl_xor_sync(0xffffffffu, d, 4);
    d += __shfl_xor_sync(0xffffffffu, d, 2);
    d += __shfl_xor_sync(0xffffffffu, d, 1);
    if (lane == 0) s_logit[wid][p] = w * d;
  }
  __syncwarp();

  float mx = -1e30f;
#pragma unroll
  for (int p = 0; p < Pp; p++) mx = fmaxf(mx, s_logit[wid][p]);

  float4 acc = make_float4(0.f, 0.f, 0.f, 0.f);
  float sum = 0.0f;
  for (int p = 0; p < Pp; p++) {
    float a = __expf(s_logit[wid][p] - mx);
    sum += a;
    int j = (p < 32) ? __shfl_sync(0xffffffffu, idxA, p)
                     : __shfl_sync(0xffffffffu, idxB, p - 32);
    float4 v4 = *(const float4*)(g_qkv + rowbase + (size_t)j * D3 + 2 * D1 + h * EMB + lane * 4);
    acc.x += a * v4.x; acc.y += a * v4.y; acc.z += a * v4.z; acc.w += a * v4.w;
  }
  float inv = 1.0f / sum;
  float4 o = make_float4(acc.x * inv, acc.y * inv, acc.z * inv, acc.w * inv);
  *(float4*)(g_attnout + (size_t)token * D1 + h * EMB + lane * 4) = o;
}

// ---------------- Kernel 4: output GEMM (tensor core, split-K x4) -----------
// partial[ks](4096x128) = attnout(4096 x [ks*256..+256)) @ Wu-slice
__global__ __launch_bounds__(256, 2) void out_gemm(const float* __restrict__ Wu) {
  __shared__ __nv_bfloat16 sXh[128 * XPAD], sXl[128 * XPAD];
  __shared__ __nv_bfloat16 sWh[64 * WPAD],  sWl[64 * WPAD];
  int bn = blockIdx.x, bm = blockIdx.y, kslice = blockIdx.z;
  int tid = threadIdx.x;
  int wid = tid >> 5, lane = tid & 31;
  int wm = wid >> 1, wn = wid & 1;
  int g = lane >> 2, t = lane & 3;

  float acc[2][4][4] = {};
  int kbase = kslice * 256;

  for (int kc = kbase; kc < kbase + 256; kc += 32) {
#pragma unroll
    for (int it = 0; it < 4; it++) {
      int idx = tid + it * 256;
      int r = idx >> 3, c4 = idx & 7;
      float4 v = *(const float4*)(g_attnout + (size_t)(bm * 128 + r) * 1024 + kc + c4 * 4);
      int o = r * XPAD + c4 * 4;
      split_bf16(v.x, sXh[o + 0], sXl[o + 0]);
      split_bf16(v.y, sXh[o + 1], sXl[o + 1]);
      split_bf16(v.z, sXh[o + 2], sXl[o + 2]);
      split_bf16(v.w, sXh[o + 3], sXl[o + 3]);
    }
#pragma unroll
    for (int it = 0; it < 2; it++) {
      int idx = tid + it * 256;
      int k = idx >> 4, c4 = idx & 15;
      float4 v = *(const float4*)(Wu + (size_t)(kc + k) * 128 + bn * 64 + c4 * 4);
      float vv[4] = {v.x, v.y, v.z, v.w};
#pragma unroll
      for (int j = 0; j < 4; j++) {
        int n = c4 * 4 + j;
        split_bf16(vv[j], sWh[n * WPAD + k], sWl[n * WPAD + k]);
      }
    }
    __syncthreads();

#pragma unroll
    for (int ks = 0; ks < 32; ks += 16) {
      uint32_t Ah[2][4], Al[2][4], Bh[4][2], Bl[4][2];
#pragma unroll
      for (int mt = 0; mt < 2; mt++) {
        int r0 = (wm * 32 + mt * 16 + g) * XPAD + ks + 2 * t;
        Ah[mt][0] = *(const uint32_t*)&sXh[r0];
        Ah[mt][1] = *(const uint32_t*)&sXh[r0 + 8 * XPAD];
        Ah[mt][2] = *(const uint32_t*)&sXh[r0 + 8];
        Ah[mt][3] = *(const uint32_t*)&sXh[r0 + 8 * XPAD + 8];
        Al[mt][0] = *(const uint32_t*)&sXl[r0];
        Al[mt][1] = *(const uint32_t*)&sXl[r0 + 8 * XPAD];
        Al[mt][2] = *(const uint32_t*)&sXl[r0 + 8];
        Al[mt][3] = *(const uint32_t*)&sXl[r0 + 8 * XPAD + 8];
      }
#pragma unroll
      for (int nt = 0; nt < 4; nt++) {
        int n0 = (wn * 32 + nt * 8 + g) * WPAD + ks + 2 * t;
        Bh[nt][0] = *(const uint32_t*)&sWh[n0];
        Bh[nt][1] = *(const uint32_t*)&sWh[n0 + 8];
        Bl[nt][0] = *(const uint32_t*)&sWl[n0];
        Bl[nt][1] = *(const uint32_t*)&sWl[n0 + 8];
      }
#pragma unroll
      for (int mt = 0; mt < 2; mt++)
#pragma unroll
        for (int nt = 0; nt < 4; nt++) {
          mma16816(acc[mt][nt], Ah[mt], Bh[nt]);
          mma16816(acc[mt][nt], Ah[mt], Bl[nt]);
          mma16816(acc[mt][nt], Al[mt], Bh[nt]);
        }
    }
    __syncthreads();
  }

  float* dst = g_part[kslice];
#pragma unroll
  for (int mt = 0; mt < 2; mt++)
#pragma unroll
    for (int nt = 0; nt < 4; nt++) {
      int row = bm * 128 + wm * 32 + mt * 16 + g;
      int col = bn * 64 + wn * 32 + nt * 8 + 2 * t;
      *(float2*)&dst[(size_t)row * 128 + col] =
          make_float2(acc[mt][nt][0], acc[mt][nt][1]);
      *(float2*)&dst[(size_t)(row + 8) * 128 + col] =
          make_float2(acc[mt][nt][2], acc[mt][nt][3]);
    }
}

// Deterministic reduce of the 4 split-K partials + bias.
__global__ __launch_bounds__(256) void out_reduce(float* __restrict__ Cout,
                                                  const float* __restrict__ bu) {
  int e4 = blockIdx.x * 256 + threadIdx.x;   // float4 index, 0..131071
  int col0 = (e4 * 4) & 127;
  float4 s = *(const float4*)(bu + col0);
#pragma unroll
  for (int ks = 0; ks < 4; ks++) {
    float4 p = *(const float4*)(g_part[ks] + e4 * 4);
    s.x += p.x; s.y += p.y; s.z += p.z; s.w += p.w;
  }
  *(float4*)(Cout + e4 * 4) = s;
}

// ---------------- launch ----------------------------------------------------
extern "C" void kernel_launch(void* const* d_in, const int* in_sizes, int n_in,
                              void* d_out, int out_size) {
  const float* x   = (const float*)d_in[0];
  const float* sp  = (const float*)d_in[1];
  const float* mv  = (const float*)d_in[2];
  const float* Wq  = (const float*)d_in[3];
  const float* Wk  = (const float*)d_in[4];
  const float* Wv  = (const float*)d_in[5];
  const float* Wu  = (const float*)d_in[6];
  const float* bu  = (const float*)d_in[7];
  float* out = (float*)d_out;

  qkv_gemm<<<dim3(48, 32), 256>>>(x, Wq, Wk, Wv);
  idxw_kernel<<<BT, 64>>>(sp, mv);
  attn_kernel<<<dim3(256, 8), 512>>>();
  out_gemm<<<dim3(2, 32, 4), 256>>>(Wu);
  out_reduce<<<512, 256>>>(out, bu);
}

// round 6
// speedup vs baseline: 1.3427x; 1.1024x over previous
#include <cuda_runtime.h>
#include <cuda_bf16.h>
#include <stdint.h>
#include <math.h>

// Problem constants
#define Tn    2048
#define EMB   128
#define NH    8
#define Mv    9      // M
#define Pp    36     // P
#define BT    4096   // B*T
#define D1    1024   // NH*EMB
#define D3    3072   // 3*D1
#define SPAD  40     // padded bf16 smem row stride (80B: ldmatrix conflict-free)

// Scratch (static device arrays; no allocation allowed)
__device__ float g_qkv[BT * D3];      // [Q(1024) | K(1024) | V(1024)] fp32
__device__ int   g_idx[BT * Pp];
__device__ float g_w[BT * Pp];
__device__ float g_part[4][BT * 128]; // split-K partials for out gemm

// pre-split bf16 hi/lo operands
__device__ __nv_bfloat16 g_Xh[BT * EMB],  g_Xl[BT * EMB];     // X
__device__ __nv_bfloat16 g_Wth[D3 * EMB], g_Wtl[D3 * EMB];    // [Wq|Wk|Wv]^T [n][k]
__device__ __nv_bfloat16 g_Wuth[EMB * D1], g_Wutl[EMB * D1];  // Wu^T [128][1024]
__device__ __nv_bfloat16 g_aoh[BT * D1], g_aol[BT * D1];      // attn out hi/lo

// ---------------- threefry-2x32 (JAX-compatible, 20 rounds) ----------------
__device__ __forceinline__ void tf2x32(uint32_t k0, uint32_t k1,
                                       uint32_t& x0, uint32_t& x1) {
  uint32_t ks2 = k0 ^ k1 ^ 0x1BD11BDAu;
  x0 += k0; x1 += k1;
#define TFR(r) { x0 += x1; x1 = (x1 << (r)) | (x1 >> (32 - (r))); x1 ^= x0; }
  TFR(13) TFR(15) TFR(26) TFR(6)
  x0 += k1;  x1 += ks2 + 1u;
  TFR(17) TFR(29) TFR(16) TFR(24)
  x0 += ks2; x1 += k0 + 2u;
  TFR(13) TFR(15) TFR(26) TFR(6)
  x0 += k0;  x1 += k1 + 3u;
  TFR(17) TFR(29) TFR(16) TFR(24)
  x0 += k1;  x1 += ks2 + 4u;
  TFR(13) TFR(15) TFR(26) TFR(6)
  x0 += ks2; x1 += k0 + 5u;
#undef TFR
}

// ---------------- MMA / ldmatrix helpers ------------------------------------
__device__ __forceinline__ void mma16816(float* c, const uint32_t* a, const uint32_t* b) {
  asm volatile(
    "mma.sync.aligned.m16n8k16.row.col.f32.bf16.bf16.f32 "
    "{%0,%1,%2,%3}, {%4,%5,%6,%7}, {%8,%9}, {%0,%1,%2,%3};"
    : "+f"(c[0]), "+f"(c[1]), "+f"(c[2]), "+f"(c[3])
    : "r"(a[0]), "r"(a[1]), "r"(a[2]), "r"(a[3]), "r"(b[0]), "r"(b[1]));
}
__device__ __forceinline__ void ldsm4(uint32_t* r, const __nv_bfloat16* p) {
  uint32_t a = (uint32_t)__cvta_generic_to_shared(p);
  asm volatile("ldmatrix.sync.aligned.m8n8.x4.shared.b16 {%0,%1,%2,%3}, [%4];"
               : "=r"(r[0]), "=r"(r[1]), "=r"(r[2]), "=r"(r[3]) : "r"(a));
}

// ---------------- Prepass: split X ------------------------------------------
__global__ __launch_bounds__(256) void split_x(const float* __restrict__ X) {
  int e4 = blockIdx.x * 256 + threadIdx.x;   // 0..131071
  float4 v = *(const float4*)(X + e4 * 4);
  float f[4] = {v.x, v.y, v.z, v.w};
  __nv_bfloat16 h[4], l[4];
#pragma unroll
  for (int i = 0; i < 4; i++) {
    h[i] = __float2bfloat16(f[i]);
    l[i] = __float2bfloat16(f[i] - __bfloat162float(h[i]));
  }
  *(uint2*)&g_Xh[e4 * 4] = *(uint2*)h;
  *(uint2*)&g_Xl[e4 * 4] = *(uint2*)l;
}

// ---------------- Prepass: transpose + split W ------------------------------
// src [K][N] fp32 -> dst [N][K] bf16 hi/lo (dst offset by nofs rows, row len Kd)
__global__ void twsplit(const float* __restrict__ src,
                        __nv_bfloat16* __restrict__ dh,
                        __nv_bfloat16* __restrict__ dl,
                        int N, int Kd, int nofs) {
  __shared__ float tile[32][33];
  int n0 = blockIdx.x * 32, k0 = blockIdx.y * 32;
  int tx = threadIdx.x;
  for (int i = threadIdx.y; i < 32; i += 8)
    tile[i][tx] = src[(size_t)(k0 + i) * N + n0 + tx];
  __syncthreads();
  for (int i = threadIdx.y; i < 32; i += 8) {
    float v = tile[tx][i];                        // src[k0+tx][n0+i]
    __nv_bfloat16 h = __float2bfloat16(v);
    __nv_bfloat16 l = __float2bfloat16(v - __bfloat162float(h));
    size_t o = (size_t)(nofs + n0 + i) * Kd + k0 + tx;
    dh[o] = h; dl[o] = l;
  }
}

// ---------------- Kernel 1: fused QKV projection (tensor core) -------------
// C(4096x3072) = X(4096x128) @ [Wq|Wk|Wv]; Q/K scaled by 1/128^0.25.
// Block 128x128, 8 warps (32x64 warp tile), bf16x3, ldmatrix feeds.
__global__ __launch_bounds__(256) void qkv_gemm() {
  __shared__ __nv_bfloat16 sAh[128 * SPAD], sAl[128 * SPAD];
  __shared__ __nv_bfloat16 sBh[128 * SPAD], sBl[128 * SPAD];
  int bn = blockIdx.x, bm = blockIdx.y;
  int n_glob0 = bn * 128;
  int tid = threadIdx.x, wid = tid >> 5, lane = tid & 31;
  int wm = wid >> 1, wn = wid & 1;
  float acc[2][8][4] = {};

  for (int kc = 0; kc < 128; kc += 32) {
#pragma unroll
    for (int it = 0; it < 2; it++) {
      int idx = tid + it * 256;             // 0..511
      int r = idx >> 2, c = idx & 3;        // row, 16B chunk (8 bf16)
      int so = r * SPAD + c * 8;
      size_t ga = (size_t)(bm * 128 + r) * 128 + kc + c * 8;
      size_t gb = (size_t)(n_glob0 + r) * 128 + kc + c * 8;
      *(uint4*)&sAh[so] = *(const uint4*)&g_Xh[ga];
      *(uint4*)&sAl[so] = *(const uint4*)&g_Xl[ga];
      *(uint4*)&sBh[so] = *(const uint4*)&g_Wth[gb];
      *(uint4*)&sBl[so] = *(const uint4*)&g_Wtl[gb];
    }
    __syncthreads();
#pragma unroll
    for (int ks = 0; ks < 32; ks += 16) {
      uint32_t Ah[2][4], Al[2][4], Bh[4][4], Bl[4][4];
#pragma unroll
      for (int mt = 0; mt < 2; mt++) {
        int off = (wm * 32 + mt * 16 + (lane & 15)) * SPAD + ks + 8 * (lane >> 4);
        ldsm4(Ah[mt], &sAh[off]);
        ldsm4(Al[mt], &sAl[off]);
      }
#pragma unroll
      for (int nb = 0; nb < 4; nb++) {
        int off = (wn * 64 + nb * 16 + 8 * ((lane >> 4) & 1) + (lane & 7)) * SPAD
                  + ks + 8 * ((lane >> 3) & 1);
        ldsm4(Bh[nb], &sBh[off]);
        ldsm4(Bl[nb], &sBl[off]);
      }
#pragma unroll
      for (int mt = 0; mt < 2; mt++)
#pragma unroll
        for (int nb = 0; nb < 4; nb++) {
          mma16816(acc[mt][nb * 2],     Ah[mt], &Bh[nb][0]);
          mma16816(acc[mt][nb * 2],     Ah[mt], &Bl[nb][0]);
          mma16816(acc[mt][nb * 2],     Al[mt], &Bh[nb][0]);
          mma16816(acc[mt][nb * 2 + 1], Ah[mt], &Bh[nb][2]);
          mma16816(acc[mt][nb * 2 + 1], Ah[mt], &Bl[nb][2]);
          mma16816(acc[mt][nb * 2 + 1], Al[mt], &Bh[nb][2]);
        }
    }
    __syncthreads();
  }

  int g = lane >> 2, t = lane & 3;
  int seg = n_glob0 >> 10;
  float scale = (seg < 2) ? 0.29730177875068026f : 1.0f; // 1/128^0.25
#pragma unroll
  for (int mt = 0; mt < 2; mt++)
#pragma unroll
    for (int nt = 0; nt < 8; nt++) {
      int row = bm * 128 + wm * 32 + mt * 16 + g;
      int col = n_glob0 + wn * 64 + nt * 8 + 2 * t;
      *(float2*)&g_qkv[(size_t)row * D3 + col] =
          make_float2(acc[mt][nt][0] * scale, acc[mt][nt][1] * scale);
      *(float2*)&g_qkv[(size_t)(row + 8) * D3 + col] =
          make_float2(acc[mt][nt][2] * scale, acc[mt][nt][3] * scale);
    }
}

// ---------------- Kernel 2: indices + weights per token --------------------
__global__ __launch_bounds__(64) void idxw_kernel(const float* __restrict__ sp,
                                                  const float* __restrict__ mvals) {
  int token = blockIdx.x;            // 0..4095
  int b = token >> 11, t = token & 2047;
  int p = threadIdx.x;
  __shared__ float s_mean[Mv];
  __shared__ float s_sigma_inv;
  __shared__ int   s_idx[Pp];
  __shared__ float s_ptsfl[Pp];
  __shared__ float s_dens[Pp][Mv];
  __shared__ float s_colinv[Mv];

  float dil = sp[0];
  if (p < Mv) {
    float off = __fmul_rn((float)(p - 4), dil);
    float mu  = __fadd_rn((float)t, off);
    mu = fminf(fmaxf(mu, 0.0f), (float)(Tn - 1));
    s_mean[p] = mu;
  }
  if (p == 0) {
    float s = sp[1] + 2.0f;                 // SIGMA_BOOST
    float sigma = log1pf(expf(s)) + 1e-7f;  // softplus + EPS
    s_sigma_inv = 1.0f / sigma;
  }
  __syncthreads();

  if (p < Pp) {
    int m = p >> 2, slot = p & 3;
    float fl = floorf(s_mean[m]);
    float val;
    if (slot == 0) val = fl;
    else if (slot == 1) val = fl + 1.0f;
    else {
      // JAX partitionable threefry (verified in R2)
      uint32_t k2a = 0u, k2b = 1u;
      tf2x32(0u, 42u, k2a, k2b);
      uint32_t i = (uint32_t)(b * 36864 + t * 18 + m * 2 + (slot - 2));
      uint32_t x0 = 0u, x1 = i;
      tf2x32(k2a, k2b, x0, x1);
      uint32_t bits = x0 ^ x1;
      val = (float)(bits & 2047u);
    }
    val = fminf(fmaxf(val, 0.0f), (float)(Tn - 1));
    int iv = (int)val;
    s_idx[p] = iv;
    s_ptsfl[p] = (float)iv;
  }
  __syncthreads();

  if (p < Pp) {
    bool dup = false;
    int my = s_idx[p];
    for (int q = 0; q < p; q++) dup |= (s_idx[q] == my);
    float inv_s = s_sigma_inv;
#pragma unroll
    for (int m = 0; m < Mv; m++) {
      float d = (s_ptsfl[p] - s_mean[m]) * inv_s;
      s_dens[p][m] = dup ? 0.0f : expf(-0.5f * d * d);
    }
  }
  __syncthreads();

  if (p < Mv) {
    float sum = 0.0f;
    for (int q = 0; q < Pp; q++) sum += s_dens[q][p];
    s_colinv[p] = 1.0f / sum;
  }
  __syncthreads();

  if (p < Pp) {
    float w = 0.0f;
#pragma unroll
    for (int m = 0; m < Mv; m++) w += s_dens[p][m] * s_colinv[m] * mvals[m];
    g_idx[token * Pp + p] = s_idx[p];
    g_w[token * Pp + p] = w;
  }
}

// ---------------- Kernel 3: gathered attention ------------------------------
// CTA = 16 consecutive tokens x 1 head (16 warps); writes bf16 hi/lo output.
__global__ __launch_bounds__(512) void attn_kernel() {
  int wid = threadIdx.x >> 5;
  int lane = threadIdx.x & 31;
  __shared__ float s_logit[16][Pp];
  int token = blockIdx.x * 16 + wid;
  int h = blockIdx.y;
  int b = token >> 11;

  float4 q = *(const float4*)(g_qkv + (size_t)token * D3 + h * EMB + lane * 4);

  const int* ip = g_idx + token * Pp;
  const float* wp = g_w + token * Pp;
  int   idxA = ip[lane];
  float wA   = wp[lane];
  int   idxB = (lane < 4) ? ip[32 + lane] : 0;
  float wB   = (lane < 4) ? wp[32 + lane] : 0.0f;

  size_t rowbase = (size_t)(b * Tn) * D3;

  for (int p = 0; p < Pp; p++) {
    int   j = (p < 32) ? __shfl_sync(0xffffffffu, idxA, p)
                       : __shfl_sync(0xffffffffu, idxB, p - 32);
    float w = (p < 32) ? __shfl_sync(0xffffffffu, wA, p)
                       : __shfl_sync(0xffffffffu, wB, p - 32);
    float4 k4 = *(const float4*)(g_qkv + rowbase + (size_t)j * D3 + D1 + h * EMB + lane * 4);
    float d = q.x * k4.x + q.y * k4.y + q.z * k4.z + q.w * k4.w;
    d += __shfl_xor_sync(0xffffffffu, d, 16);
    d += __shfl_xor_sync(0xffffffffu, d, 8);
    d += __shfl_xor_sync(0xffffffffu, d, 4);
    d += __shfl_xor_sync(0xffffffffu, d, 2);
    d += __shfl_xor_sync(0xffffffffu, d, 1);
    if (lane == 0) s_logit[wid][p] = w * d;
  }
  __syncwarp();

  float mx = -1e30f;
#pragma unroll
  for (int p = 0; p < Pp; p++) mx = fmaxf(mx, s_logit[wid][p]);

  float4 acc = make_float4(0.f, 0.f, 0.f, 0.f);
  float sum = 0.0f;
  for (int p = 0; p < Pp; p++) {
    float a = __expf(s_logit[wid][p] - mx);
    sum += a;
    int j = (p < 32) ? __shfl_sync(0xffffffffu, idxA, p)
                     : __shfl_sync(0xffffffffu, idxB, p - 32);
    float4 v4 = *(const float4*)(g_qkv + rowbase + (size_t)j * D3 + 2 * D1 + h * EMB + lane * 4);
    acc.x += a * v4.x; acc.y += a * v4.y; acc.z += a * v4.z; acc.w += a * v4.w;
  }
  float inv = 1.0f / sum;
  float o[4] = {acc.x * inv, acc.y * inv, acc.z * inv, acc.w * inv};
  __nv_bfloat16 hh[4], ll[4];
#pragma unroll
  for (int i = 0; i < 4; i++) {
    hh[i] = __float2bfloat16(o[i]);
    ll[i] = __float2bfloat16(o[i] - __bfloat162float(hh[i]));
  }
  size_t base = (size_t)token * D1 + h * EMB + lane * 4;
  *(uint2*)&g_aoh[base] = *(uint2*)hh;
  *(uint2*)&g_aol[base] = *(uint2*)ll;
}

// ---------------- Kernel 4: output GEMM (tensor core, split-K x4) -----------
// partial[ks](4096x128) = attnout(4096 x [ks*256..+256)) @ Wu-slice
__global__ __launch_bounds__(256) void out_gemm() {
  __shared__ __nv_bfloat16 sAh[128 * SPAD], sAl[128 * SPAD];
  __shared__ __nv_bfloat16 sBh[128 * SPAD], sBl[128 * SPAD];
  int bm = blockIdx.x, kslice = blockIdx.y;
  int tid = threadIdx.x, wid = tid >> 5, lane = tid & 31;
  int wm = wid >> 1, wn = wid & 1;
  float acc[2][8][4] = {};
  int kbase = kslice * 256;

  for (int kc = kbase; kc < kbase + 256; kc += 32) {
#pragma unroll
    for (int it = 0; it < 2; it++) {
      int idx = tid + it * 256;
      int r = idx >> 2, c = idx & 3;
      int so = r * SPAD + c * 8;
      size_t ga = (size_t)(bm * 128 + r) * D1 + kc + c * 8;
      size_t gb = (size_t)r * D1 + kc + c * 8;   // Wu^T rows = n (128)
      *(uint4*)&sAh[so] = *(const uint4*)&g_aoh[ga];
      *(uint4*)&sAl[so] = *(const uint4*)&g_aol[ga];
      *(uint4*)&sBh[so] = *(const uint4*)&g_Wuth[gb];
      *(uint4*)&sBl[so] = *(const uint4*)&g_Wutl[gb];
    }
    __syncthreads();
#pragma unroll
    for (int ks = 0; ks < 32; ks += 16) {
      uint32_t Ah[2][4], Al[2][4], Bh[4][4], Bl[4][4];
#pragma unroll
      for (int mt = 0; mt < 2; mt++) {
        int off = (wm * 32 + mt * 16 + (lane & 15)) * SPAD + ks + 8 * (lane >> 4);
        ldsm4(Ah[mt], &sAh[off]);
        ldsm4(Al[mt], &sAl[off]);
      }
#pragma unroll
      for (int nb = 0; nb < 4; nb++) {
        int off = (wn * 64 + nb * 16 + 8 * ((lane >> 4) & 1) + (lane & 7)) * SPAD
                  + ks + 8 * ((lane >> 3) & 1);
        ldsm4(Bh[nb], &sBh[off]);
        ldsm4(Bl[nb], &sBl[off]);
      }
#pragma unroll
      for (int mt = 0; mt < 2; mt++)
#pragma unroll
        for (int nb = 0; nb < 4; nb++) {
          mma16816(acc[mt][nb * 2],     Ah[mt], &Bh[nb][0]);
          mma16816(acc[mt][nb * 2],     Ah[mt], &Bl[nb][0]);
          mma16816(acc[mt][nb * 2],     Al[mt], &Bh[nb][0]);
          mma16816(acc[mt][nb * 2 + 1], Ah[mt], &Bh[nb][2]);
          mma16816(acc[mt][nb * 2 + 1], Ah[mt], &Bl[nb][2]);
          mma16816(acc[mt][nb * 2 + 1], Al[mt], &Bh[nb][2]);
        }
    }
    __syncthreads();
  }

  int g = lane >> 2, t = lane & 3;
  float* dst = g_part[kslice];
#pragma unroll
  for (int mt = 0; mt < 2; mt++)
#pragma unroll
    for (int nt = 0; nt < 8; nt++) {
      int row = bm * 128 + wm * 32 + mt * 16 + g;
      int col = wn * 64 + nt * 8 + 2 * t;
      *(float2*)&dst[(size_t)row * 128 + col] =
          make_float2(acc[mt][nt][0], acc[mt][nt][1]);
      *(float2*)&dst[(size_t)(row + 8) * 128 + col] =
          make_float2(acc[mt][nt][2], acc[mt][nt][3]);
    }
}

// Deterministic reduce of the 4 split-K partials + bias.
__global__ __launch_bounds__(256) void out_reduce(float* __restrict__ Cout,
                                                  const float* __restrict__ bu) {
  int e4 = blockIdx.x * 256 + threadIdx.x;   // float4 index, 0..131071
  int col0 = (e4 * 4) & 127;
  float4 s = *(const float4*)(bu + col0);
#pragma unroll
  for (int ks = 0; ks < 4; ks++) {
    float4 p = *(const float4*)(g_part[ks] + e4 * 4);
    s.x += p.x; s.y += p.y; s.z += p.z; s.w += p.w;
  }
  *(float4*)(Cout + e4 * 4) = s;
}

// ---------------- launch ----------------------------------------------------
extern "C" void kernel_launch(void* const* d_in, const int* in_sizes, int n_in,
                              void* d_out, int out_size) {
  const float* x   = (const float*)d_in[0];
  const float* sp  = (const float*)d_in[1];
  const float* mv  = (const float*)d_in[2];
  const float* Wq  = (const float*)d_in[3];
  const float* Wk  = (const float*)d_in[4];
  const float* Wv  = (const float*)d_in[5];
  const float* Wu  = (const float*)d_in[6];
  const float* bu  = (const float*)d_in[7];
  float* out = (float*)d_out;

  __nv_bfloat16 *wth, *wtl, *wuth, *wutl;
  cudaGetSymbolAddress((void**)&wth,  g_Wth);
  cudaGetSymbolAddress((void**)&wtl,  g_Wtl);
  cudaGetSymbolAddress((void**)&wuth, g_Wuth);
  cudaGetSymbolAddress((void**)&wutl, g_Wutl);

  split_x<<<512, 256>>>(x);
  twsplit<<<dim3(32, 4), dim3(32, 8)>>>(Wq, wth, wtl, 1024, 128, 0);
  twsplit<<<dim3(32, 4), dim3(32, 8)>>>(Wk, wth, wtl, 1024, 128, 1024);
  twsplit<<<dim3(32, 4), dim3(32, 8)>>>(Wv, wth, wtl, 1024, 128, 2048);
  twsplit<<<dim3(4, 32), dim3(32, 8)>>>(Wu, wuth, wutl, 128, 1024, 0);
  qkv_gemm<<<dim3(24, 32), 256>>>();
  idxw_kernel<<<BT, 64>>>(sp, mv);
  attn_kernel<<<dim3(256, 8), 512>>>();
  out_gemm<<<dim3(32, 4), 256>>>();
  out_reduce<<<512, 256>>>(out, bu);
}

// round 7
// speedup vs baseline: 1.4746x; 1.0982x over previous
#include <cuda_runtime.h>
#include <cuda_bf16.h>
#include <cuda_fp16.h>
#include <stdint.h>
#include <math.h>

// Problem constants
#define Tn    2048
#define EMB   128
#define NH    8
#define Mv    9      // M
#define Pp    36     // P
#define BT    4096   // B*T
#define D1    1024   // NH*EMB
#define D3    3072   // 3*D1
#define SPAD  40     // padded bf16 smem row stride (80B: ldmatrix conflict-free)

// Scratch (static device arrays; no allocation allowed)
__device__ float g_q[BT * D1];        // Q fp32 (scaled), token-major
__device__ __half g_K[2 * NH * Tn * EMB];  // K fp16 (scaled), [b][h][t][d]
__device__ __half g_V[2 * NH * Tn * EMB];  // V fp16,          [b][h][t][d]
__device__ int   g_idx[BT * Pp];
__device__ float g_w[BT * Pp];
__device__ float g_part[4][BT * 128]; // split-K partials for out gemm

// pre-split bf16 hi/lo operands
__device__ __nv_bfloat16 g_Xh[BT * EMB],  g_Xl[BT * EMB];     // X
__device__ __nv_bfloat16 g_Wth[D3 * EMB], g_Wtl[D3 * EMB];    // [Wq|Wk|Wv]^T [n][k]
__device__ __nv_bfloat16 g_Wuth[EMB * D1], g_Wutl[EMB * D1];  // Wu^T [128][1024]
__device__ __nv_bfloat16 g_aoh[BT * D1], g_aol[BT * D1];      // attn out hi/lo

// ---------------- threefry-2x32 (JAX-compatible, 20 rounds) ----------------
__device__ __forceinline__ void tf2x32(uint32_t k0, uint32_t k1,
                                       uint32_t& x0, uint32_t& x1) {
  uint32_t ks2 = k0 ^ k1 ^ 0x1BD11BDAu;
  x0 += k0; x1 += k1;
#define TFR(r) { x0 += x1; x1 = (x1 << (r)) | (x1 >> (32 - (r))); x1 ^= x0; }
  TFR(13) TFR(15) TFR(26) TFR(6)
  x0 += k1;  x1 += ks2 + 1u;
  TFR(17) TFR(29) TFR(16) TFR(24)
  x0 += ks2; x1 += k0 + 2u;
  TFR(13) TFR(15) TFR(26) TFR(6)
  x0 += k0;  x1 += k1 + 3u;
  TFR(17) TFR(29) TFR(16) TFR(24)
  x0 += k1;  x1 += ks2 + 4u;
  TFR(13) TFR(15) TFR(26) TFR(6)
  x0 += ks2; x1 += k0 + 5u;
#undef TFR
}

// ---------------- MMA / ldmatrix helpers ------------------------------------
__device__ __forceinline__ void mma16816(float* c, const uint32_t* a, const uint32_t* b) {
  asm volatile(
    "mma.sync.aligned.m16n8k16.row.col.f32.bf16.bf16.f32 "
    "{%0,%1,%2,%3}, {%4,%5,%6,%7}, {%8,%9}, {%0,%1,%2,%3};"
    : "+f"(c[0]), "+f"(c[1]), "+f"(c[2]), "+f"(c[3])
    : "r"(a[0]), "r"(a[1]), "r"(a[2]), "r"(a[3]), "r"(b[0]), "r"(b[1]));
}
__device__ __forceinline__ void ldsm4(uint32_t* r, const __nv_bfloat16* p) {
  uint32_t a = (uint32_t)__cvta_generic_to_shared(p);
  asm volatile("ldmatrix.sync.aligned.m8n8.x4.shared.b16 {%0,%1,%2,%3}, [%4];"
               : "=r"(r[0]), "=r"(r[1]), "=r"(r[2]), "=r"(r[3]) : "r"(a));
}

// ---------------- Fused prepass: split X + transpose/split all weights ------
__device__ void twsplit_body(const float* __restrict__ src,
                             __nv_bfloat16* __restrict__ dh,
                             __nv_bfloat16* __restrict__ dl,
                             int N, int Kd, int nofs, int bx, int by,
                             float* tile /*32x33*/) {
  int tx = threadIdx.x & 31, ty = threadIdx.x >> 5;   // 32 x 8
  int n0 = bx * 32, k0 = by * 32;
  for (int i = ty; i < 32; i += 8)
    tile[i * 33 + tx] = src[(size_t)(k0 + i) * N + n0 + tx];
  __syncthreads();
  for (int i = ty; i < 32; i += 8) {
    float v = tile[tx * 33 + i];                 // src[k0+tx][n0+i]
    __nv_bfloat16 h = __float2bfloat16(v);
    __nv_bfloat16 l = __float2bfloat16(v - __bfloat162float(h));
    size_t o = (size_t)(nofs + n0 + i) * Kd + k0 + tx;
    dh[o] = h; dl[o] = l;
  }
}

__global__ __launch_bounds__(256) void prepass(const float* __restrict__ X,
                                               const float* __restrict__ Wq,
                                               const float* __restrict__ Wk,
                                               const float* __restrict__ Wv,
                                               const float* __restrict__ Wu) {
  __shared__ float tile[32 * 33];
  int bid = blockIdx.x;
  if (bid < 512) {                      // split X: 512 * 256 float4 = 512K floats
    int e4 = bid * 256 + threadIdx.x;
    float4 v = *(const float4*)(X + e4 * 4);
    float f[4] = {v.x, v.y, v.z, v.w};
    __nv_bfloat16 h[4], l[4];
#pragma unroll
    for (int i = 0; i < 4; i++) {
      h[i] = __float2bfloat16(f[i]);
      l[i] = __float2bfloat16(f[i] - __bfloat162float(h[i]));
    }
    *(uint2*)&g_Xh[e4 * 4] = *(uint2*)h;
    *(uint2*)&g_Xl[e4 * 4] = *(uint2*)l;
  } else {
    int r = bid - 512;                  // 0..511
    int which = r >> 7, sub = r & 127;
    if (which < 3) {                    // Wq/Wk/Wv: N=1024, Kd=128, 32x4 blocks
      const float* src = (which == 0) ? Wq : ((which == 1) ? Wk : Wv);
      twsplit_body(src, g_Wth, g_Wtl, 1024, 128, which * 1024,
                   sub & 31, sub >> 5, tile);
    } else {                            // Wu: N=128, Kd=1024, 4x32 blocks
      twsplit_body(Wu, g_Wuth, g_Wutl, 128, 1024, 0,
                   sub & 3, sub >> 2, tile);
    }
  }
}

// ---------------- Kernel 1: fused QKV projection (tensor core) -------------
// C(4096x3072) = X @ [Wq|Wk|Wv]; Q fp32 token-major (scaled), K/V fp16
// head-major (K scaled). Block 128x128, 8 warps, bf16x3, ldmatrix feeds.
__global__ __launch_bounds__(256) void qkv_gemm() {
  __shared__ __nv_bfloat16 sAh[128 * SPAD], sAl[128 * SPAD];
  __shared__ __nv_bfloat16 sBh[128 * SPAD], sBl[128 * SPAD];
  int bn = blockIdx.x, bm = blockIdx.y;
  int n_glob0 = bn * 128;
  int tid = threadIdx.x, wid = tid >> 5, lane = tid & 31;
  int wm = wid >> 1, wn = wid & 1;
  float acc[2][8][4] = {};

  for (int kc = 0; kc < 128; kc += 32) {
#pragma unroll
    for (int it = 0; it < 2; it++) {
      int idx = tid + it * 256;             // 0..511
      int r = idx >> 2, c = idx & 3;        // row, 16B chunk (8 bf16)
      int so = r * SPAD + c * 8;
      size_t ga = (size_t)(bm * 128 + r) * 128 + kc + c * 8;
      size_t gb = (size_t)(n_glob0 + r) * 128 + kc + c * 8;
      *(uint4*)&sAh[so] = *(const uint4*)&g_Xh[ga];
      *(uint4*)&sAl[so] = *(const uint4*)&g_Xl[ga];
      *(uint4*)&sBh[so] = *(const uint4*)&g_Wth[gb];
      *(uint4*)&sBl[so] = *(const uint4*)&g_Wtl[gb];
    }
    __syncthreads();
#pragma unroll
    for (int ks = 0; ks < 32; ks += 16) {
      uint32_t Ah[2][4], Al[2][4], Bh[4][4], Bl[4][4];
#pragma unroll
      for (int mt = 0; mt < 2; mt++) {
        int off = (wm * 32 + mt * 16 + (lane & 15)) * SPAD + ks + 8 * (lane >> 4);
        ldsm4(Ah[mt], &sAh[off]);
        ldsm4(Al[mt], &sAl[off]);
      }
#pragma unroll
      for (int nb = 0; nb < 4; nb++) {
        int off = (wn * 64 + nb * 16 + 8 * ((lane >> 4) & 1) + (lane & 7)) * SPAD
                  + ks + 8 * ((lane >> 3) & 1);
        ldsm4(Bh[nb], &sBh[off]);
        ldsm4(Bl[nb], &sBl[off]);
      }
#pragma unroll
      for (int mt = 0; mt < 2; mt++)
#pragma unroll
        for (int nb = 0; nb < 4; nb++) {
          mma16816(acc[mt][nb * 2],     Ah[mt], &Bh[nb][0]);
          mma16816(acc[mt][nb * 2],     Ah[mt], &Bl[nb][0]);
          mma16816(acc[mt][nb * 2],     Al[mt], &Bh[nb][0]);
          mma16816(acc[mt][nb * 2 + 1], Ah[mt], &Bh[nb][2]);
          mma16816(acc[mt][nb * 2 + 1], Ah[mt], &Bl[nb][2]);
          mma16816(acc[mt][nb * 2 + 1], Al[mt], &Bh[nb][2]);
        }
    }
    __syncthreads();
  }

  int g = lane >> 2, t = lane & 3;
  int seg = n_glob0 >> 10;                          // 0=Q 1=K 2=V
  float scale = (seg < 2) ? 0.29730177875068026f : 1.0f; // 1/128^0.25
#pragma unroll
  for (int mt = 0; mt < 2; mt++)
#pragma unroll
    for (int nt = 0; nt < 8; nt++) {
      int row = bm * 128 + wm * 32 + mt * 16 + g;   // token (row, row+8)
      int col = n_glob0 + wn * 64 + nt * 8 + 2 * t;
      float2 v0 = make_float2(acc[mt][nt][0] * scale, acc[mt][nt][1] * scale);
      float2 v1 = make_float2(acc[mt][nt][2] * scale, acc[mt][nt][3] * scale);
      if (seg == 0) {
        *(float2*)&g_q[(size_t)row * D1 + col] = v0;
        *(float2*)&g_q[(size_t)(row + 8) * D1 + col] = v1;
      } else {
        int c = col & 1023, h = c >> 7, d = c & 127;
        int b = row >> 11, tt = row & 2047;
        __half* dst = (seg == 1) ? g_K : g_V;
        size_t base = ((size_t)(b * NH + h) * Tn + tt) * EMB + d;
        *(__half2*)&dst[base] = __float22half2_rn(v0);
        *(__half2*)&dst[base + 8 * EMB] = __float22half2_rn(v1);
      }
    }
}

// ---------------- Kernel 2: indices + weights (2 tokens / 128-thr block) ---
__global__ __launch_bounds__(128) void idxw_kernel(const float* __restrict__ sp,
                                                   const float* __restrict__ mvals) {
  int sub = threadIdx.x >> 6;          // 0/1
  int p = threadIdx.x & 63;
  int token = blockIdx.x * 2 + sub;    // 0..4095
  int b = token >> 11, t = token & 2047;
  __shared__ float s_mean[2][Mv];
  __shared__ float s_sigma_inv;
  __shared__ int   s_idx[2][Pp];
  __shared__ float s_ptsfl[2][Pp];
  __shared__ float s_dens[2][Pp][Mv];
  __shared__ float s_colinv[2][Mv];

  float dil = sp[0];
  if (p < Mv) {
    float off = __fmul_rn((float)(p - 4), dil);
    float mu  = __fadd_rn((float)t, off);
    mu = fminf(fmaxf(mu, 0.0f), (float)(Tn - 1));
    s_mean[sub][p] = mu;
  }
  if (threadIdx.x == 0) {
    float s = sp[1] + 2.0f;                 // SIGMA_BOOST
    float sigma = log1pf(expf(s)) + 1e-7f;  // softplus + EPS
    s_sigma_inv = 1.0f / sigma;
  }
  __syncthreads();

  if (p < Pp) {
    int m = p >> 2, slot = p & 3;
    float fl = floorf(s_mean[sub][m]);
    float val;
    if (slot == 0) val = fl;
    else if (slot == 1) val = fl + 1.0f;
    else {
      // JAX partitionable threefry (verified in R2)
      uint32_t k2a = 0u, k2b = 1u;
      tf2x32(0u, 42u, k2a, k2b);
      uint32_t i = (uint32_t)(b * 36864 + t * 18 + m * 2 + (slot - 2));
      uint32_t x0 = 0u, x1 = i;
      tf2x32(k2a, k2b, x0, x1);
      uint32_t bits = x0 ^ x1;
      val = (float)(bits & 2047u);
    }
    val = fminf(fmaxf(val, 0.0f), (float)(Tn - 1));
    int iv = (int)val;
    s_idx[sub][p] = iv;
    s_ptsfl[sub][p] = (float)iv;
  }
  __syncthreads();

  if (p < Pp) {
    bool dup = false;
    int my = s_idx[sub][p];
    for (int q = 0; q < p; q++) dup |= (s_idx[sub][q] == my);
    float inv_s = s_sigma_inv;
#pragma unroll
    for (int m = 0; m < Mv; m++) {
      float d = (s_ptsfl[sub][p] - s_mean[sub][m]) * inv_s;
      s_dens[sub][p][m] = dup ? 0.0f : expf(-0.5f * d * d);
    }
  }
  __syncthreads();

  if (p < Mv) {
    float sum = 0.0f;
    for (int q = 0; q < Pp; q++) sum += s_dens[sub][q][p];
    s_colinv[sub][p] = 1.0f / sum;
  }
  __syncthreads();

  if (p < Pp) {
    float w = 0.0f;
#pragma unroll
    for (int m = 0; m < Mv; m++) w += s_dens[sub][p][m] * s_colinv[sub][m] * mvals[m];
    g_idx[token * Pp + p] = s_idx[sub][p];
    g_w[token * Pp + p] = w;
  }
}

// ---------------- Kernel 3: gathered attention (fp16 K/V, head-major) ------
// CTA = 16 consecutive tokens x 1 head (16 warps); writes bf16 hi/lo output.
__global__ __launch_bounds__(512) void attn_kernel() {
  int wid = threadIdx.x >> 5;
  int lane = threadIdx.x & 31;
  __shared__ float s_logit[16][Pp];
  int token = blockIdx.x * 16 + wid;
  int h = blockIdx.y;
  int b = token >> 11;

  float4 q = *(const float4*)(g_q + (size_t)token * D1 + h * EMB + lane * 4);

  const int* ip = g_idx + token * Pp;
  const float* wp = g_w + token * Pp;
  int   idxA = ip[lane];
  float wA   = wp[lane];
  int   idxB = (lane < 4) ? ip[32 + lane] : 0;
  float wB   = (lane < 4) ? wp[32 + lane] : 0.0f;

  const __half* kb = g_K + (size_t)(b * NH + h) * Tn * EMB;
  const __half* vb = g_V + (size_t)(b * NH + h) * Tn * EMB;

  for (int p = 0; p < Pp; p++) {
    int   j = (p < 32) ? __shfl_sync(0xffffffffu, idxA, p)
                       : __shfl_sync(0xffffffffu, idxB, p - 32);
    float w = (p < 32) ? __shfl_sync(0xffffffffu, wA, p)
                       : __shfl_sync(0xffffffffu, wB, p - 32);
    uint2 kr = *(const uint2*)&kb[(size_t)j * EMB + lane * 4];
    float2 f01 = __half22float2(*(__half2*)&kr.x);
    float2 f23 = __half22float2(*(__half2*)&kr.y);
    float d = q.x * f01.x + q.y * f01.y + q.z * f23.x + q.w * f23.y;
    d += __shfl_xor_sync(0xffffffffu, d, 16);
    d += __shfl_xor_sync(0xffffffffu, d, 8);
    d += __shfl_xor_sync(0xffffffffu, d, 4);
    d += __shfl_xor_sync(0xffffffffu, d, 2);
    d += __shfl_xor_sync(0xffffffffu, d, 1);
    if (lane == 0) s_logit[wid][p] = w * d;
  }
  __syncwarp();

  float mx = -1e30f;
#pragma unroll
  for (int p = 0; p < Pp; p++) mx = fmaxf(mx, s_logit[wid][p]);

  float4 acc = make_float4(0.f, 0.f, 0.f, 0.f);
  float sum = 0.0f;
  for (int p = 0; p < Pp; p++) {
    float a = __expf(s_logit[wid][p] - mx);
    sum += a;
    int j = (p < 32) ? __shfl_sync(0xffffffffu, idxA, p)
                     : __shfl_sync(0xffffffffu, idxB, p - 32);
    uint2 vr = *(const uint2*)&vb[(size_t)j * EMB + lane * 4];
    float2 f01 = __half22float2(*(__half2*)&vr.x);
    float2 f23 = __half22float2(*(__half2*)&vr.y);
    acc.x += a * f01.x; acc.y += a * f01.y; acc.z += a * f23.x; acc.w += a * f23.y;
  }
  float inv = 1.0f / sum;
  float o[4] = {acc.x * inv, acc.y * inv, acc.z * inv, acc.w * inv};
  __nv_bfloat16 hh[4], ll[4];
#pragma unroll
  for (int i = 0; i < 4; i++) {
    hh[i] = __float2bfloat16(o[i]);
    ll[i] = __float2bfloat16(o[i] - __bfloat162float(hh[i]));
  }
  size_t base = (size_t)token * D1 + h * EMB + lane * 4;
  *(uint2*)&g_aoh[base] = *(uint2*)hh;
  *(uint2*)&g_aol[base] = *(uint2*)ll;
}

// ---------------- Kernel 4: output GEMM (tensor core, split-K x4) -----------
__global__ __launch_bounds__(256) void out_gemm() {
  __shared__ __nv_bfloat16 sAh[128 * SPAD], sAl[128 * SPAD];
  __shared__ __nv_bfloat16 sBh[128 * SPAD], sBl[128 * SPAD];
  int bm = blockIdx.x, kslice = blockIdx.y;
  int tid = threadIdx.x, wid = tid >> 5, lane = tid & 31;
  int wm = wid >> 1, wn = wid & 1;
  float acc[2][8][4] = {};
  int kbase = kslice * 256;

  for (int kc = kbase; kc < kbase + 256; kc += 32) {
#pragma unroll
    for (int it = 0; it < 2; it++) {
      int idx = tid + it * 256;
      int r = idx >> 2, c = idx & 3;
      int so = r * SPAD + c * 8;
      size_t ga = (size_t)(bm * 128 + r) * D1 + kc + c * 8;
      size_t gb = (size_t)r * D1 + kc + c * 8;   // Wu^T rows = n (128)
      *(uint4*)&sAh[so] = *(const uint4*)&g_aoh[ga];
      *(uint4*)&sAl[so] = *(const uint4*)&g_aol[ga];
      *(uint4*)&sBh[so] = *(const uint4*)&g_Wuth[gb];
      *(uint4*)&sBl[so] = *(const uint4*)&g_Wutl[gb];
    }
    __syncthreads();
#pragma unroll
    for (int ks = 0; ks < 32; ks += 16) {
      uint32_t Ah[2][4], Al[2][4], Bh[4][4], Bl[4][4];
#pragma unroll
      for (int mt = 0; mt < 2; mt++) {
        int off = (wm * 32 + mt * 16 + (lane & 15)) * SPAD + ks + 8 * (lane >> 4);
        ldsm4(Ah[mt], &sAh[off]);
        ldsm4(Al[mt], &sAl[off]);
      }
#pragma unroll
      for (int nb = 0; nb < 4; nb++) {
        int off = (wn * 64 + nb * 16 + 8 * ((lane >> 4) & 1) + (lane & 7)) * SPAD
                  + ks + 8 * ((lane >> 3) & 1);
        ldsm4(Bh[nb], &sBh[off]);
        ldsm4(Bl[nb], &sBl[off]);
      }
#pragma unroll
      for (int mt = 0; mt < 2; mt++)
#pragma unroll
        for (int nb = 0; nb < 4; nb++) {
          mma16816(acc[mt][nb * 2],     Ah[mt], &Bh[nb][0]);
          mma16816(acc[mt][nb * 2],     Ah[mt], &Bl[nb][0]);
          mma16816(acc[mt][nb * 2],     Al[mt], &Bh[nb][0]);
          mma16816(acc[mt][nb * 2 + 1], Ah[mt], &Bh[nb][2]);
          mma16816(acc[mt][nb * 2 + 1], Ah[mt], &Bl[nb][2]);
          mma16816(acc[mt][nb * 2 + 1], Al[mt], &Bh[nb][2]);
        }
    }
    __syncthreads();
  }

  int g = lane >> 2, t = lane & 3;
  float* dst = g_part[kslice];
#pragma unroll
  for (int mt = 0; mt < 2; mt++)
#pragma unroll
    for (int nt = 0; nt < 8; nt++) {
      int row = bm * 128 + wm * 32 + mt * 16 + g;
      int col = wn * 64 + nt * 8 + 2 * t;
      *(float2*)&dst[(size_t)row * 128 + col] =
          make_float2(acc[mt][nt][0], acc[mt][nt][1]);
      *(float2*)&dst[(size_t)(row + 8) * 128 + col] =
          make_float2(acc[mt][nt][2], acc[mt][nt][3]);
    }
}

// Deterministic reduce of the 4 split-K partials + bias.
__global__ __launch_bounds__(256) void out_reduce(float* __restrict__ Cout,
                                                  const float* __restrict__ bu) {
  int e4 = blockIdx.x * 256 + threadIdx.x;   // float4 index, 0..131071
  int col0 = (e4 * 4) & 127;
  float4 s = *(const float4*)(bu + col0);
#pragma unroll
  for (int ks = 0; ks < 4; ks++) {
    float4 p = *(const float4*)(g_part[ks] + e4 * 4);
    s.x += p.x; s.y += p.y; s.z += p.z; s.w += p.w;
  }
  *(float4*)(Cout + e4 * 4) = s;
}

// ---------------- launch ----------------------------------------------------
extern "C" void kernel_launch(void* const* d_in, const int* in_sizes, int n_in,
                              void* d_out, int out_size) {
  const float* x   = (const float*)d_in[0];
  const float* sp  = (const float*)d_in[1];
  const float* mv  = (const float*)d_in[2];
  const float* Wq  = (const float*)d_in[3];
  const float* Wk  = (const float*)d_in[4];
  const float* Wv  = (const float*)d_in[5];
  const float* Wu  = (const float*)d_in[6];
  const float* bu  = (const float*)d_in[7];
  float* out = (float*)d_out;

  prepass<<<1024, 256>>>(x, Wq, Wk, Wv, Wu);
  idxw_kernel<<<2048, 128>>>(sp, mv);
  qkv_gemm<<<dim3(24, 32), 256>>>();
  attn_kernel<<<dim3(256, 8), 512>>>();
  out_gemm<<<dim3(32, 4), 256>>>();
  out_reduce<<<512, 256>>>(out, bu);
}

// round 8
// speedup vs baseline: 1.8467x; 1.2524x over previous
#include <cuda_runtime.h>
#include <cuda_bf16.h>
#include <cuda_fp16.h>
#include <stdint.h>
#include <math.h>

// Problem constants
#define Tn    2048
#define EMB   128
#define NH    8
#define Mv    9      // M
#define Pp    36     // P
#define BT    4096   // B*T
#define D1    1024   // NH*EMB
#define D3    3072   // 3*D1
#define SPAD  40     // padded bf16 smem row stride (80B: ldmatrix conflict-free)

// Scratch (static device arrays; no allocation allowed)
__device__ float g_q[BT * D1];        // Q fp32 (scaled), token-major
__device__ __half g_K[2 * NH * Tn * EMB];  // K fp16 (scaled), [b][h][t][d]
__device__ __half g_V[2 * NH * Tn * EMB];  // V fp16,          [b][h][t][d]
__device__ int   g_idx[BT * Pp];
__device__ float g_w[BT * Pp];
__device__ float g_part[4][BT * 128]; // split-K partials for out gemm

// pre-split bf16 hi/lo operands
__device__ __nv_bfloat16 g_Xh[BT * EMB],  g_Xl[BT * EMB];     // X
__device__ __nv_bfloat16 g_Wth[D3 * EMB], g_Wtl[D3 * EMB];    // [Wq|Wk|Wv]^T [n][k]
__device__ __nv_bfloat16 g_Wuth[EMB * D1], g_Wutl[EMB * D1];  // Wu^T [128][1024]
__device__ __nv_bfloat16 g_aoh[BT * D1], g_aol[BT * D1];      // attn out hi/lo

// ---------------- threefry-2x32 (JAX-compatible, 20 rounds) ----------------
__device__ __forceinline__ void tf2x32(uint32_t k0, uint32_t k1,
                                       uint32_t& x0, uint32_t& x1) {
  uint32_t ks2 = k0 ^ k1 ^ 0x1BD11BDAu;
  x0 += k0; x1 += k1;
#define TFR(r) { x0 += x1; x1 = (x1 << (r)) | (x1 >> (32 - (r))); x1 ^= x0; }
  TFR(13) TFR(15) TFR(26) TFR(6)
  x0 += k1;  x1 += ks2 + 1u;
  TFR(17) TFR(29) TFR(16) TFR(24)
  x0 += ks2; x1 += k0 + 2u;
  TFR(13) TFR(15) TFR(26) TFR(6)
  x0 += k0;  x1 += k1 + 3u;
  TFR(17) TFR(29) TFR(16) TFR(24)
  x0 += k1;  x1 += ks2 + 4u;
  TFR(13) TFR(15) TFR(26) TFR(6)
  x0 += ks2; x1 += k0 + 5u;
#undef TFR
}

// ---------------- MMA / ldmatrix helpers ------------------------------------
__device__ __forceinline__ void mma16816(float* c, const uint32_t* a, const uint32_t* b) {
  asm volatile(
    "mma.sync.aligned.m16n8k16.row.col.f32.bf16.bf16.f32 "
    "{%0,%1,%2,%3}, {%4,%5,%6,%7}, {%8,%9}, {%0,%1,%2,%3};"
    : "+f"(c[0]), "+f"(c[1]), "+f"(c[2]), "+f"(c[3])
    : "r"(a[0]), "r"(a[1]), "r"(a[2]), "r"(a[3]), "r"(b[0]), "r"(b[1]));
}
__device__ __forceinline__ void ldsm4(uint32_t* r, const __nv_bfloat16* p) {
  uint32_t a = (uint32_t)__cvta_generic_to_shared(p);
  asm volatile("ldmatrix.sync.aligned.m8n8.x4.shared.b16 {%0,%1,%2,%3}, [%4];"
               : "=r"(r[0]), "=r"(r[1]), "=r"(r[2]), "=r"(r[3]) : "r"(a));
}

// fp16 uint4 (8 halves) dot with 8 fp32 q values
__device__ __forceinline__ float dot8(const float* q, uint4 k) {
  float2 a0 = __half22float2(*(__half2*)&k.x);
  float2 a1 = __half22float2(*(__half2*)&k.y);
  float2 a2 = __half22float2(*(__half2*)&k.z);
  float2 a3 = __half22float2(*(__half2*)&k.w);
  return q[0]*a0.x + q[1]*a0.y + q[2]*a1.x + q[3]*a1.y +
         q[4]*a2.x + q[5]*a2.y + q[6]*a3.x + q[7]*a3.y;
}

// ---------------- Fused prepass: split X + transpose/split all weights ------
__device__ void twsplit_body(const float* __restrict__ src,
                             __nv_bfloat16* __restrict__ dh,
                             __nv_bfloat16* __restrict__ dl,
                             int N, int Kd, int nofs, int bx, int by,
                             float* tile /*32x33*/) {
  int tx = threadIdx.x & 31, ty = threadIdx.x >> 5;   // 32 x 8
  int n0 = bx * 32, k0 = by * 32;
  for (int i = ty; i < 32; i += 8)
    tile[i * 33 + tx] = src[(size_t)(k0 + i) * N + n0 + tx];
  __syncthreads();
  for (int i = ty; i < 32; i += 8) {
    float v = tile[tx * 33 + i];                 // src[k0+tx][n0+i]
    __nv_bfloat16 h = __float2bfloat16(v);
    __nv_bfloat16 l = __float2bfloat16(v - __bfloat162float(h));
    size_t o = (size_t)(nofs + n0 + i) * Kd + k0 + tx;
    dh[o] = h; dl[o] = l;
  }
}

__global__ __launch_bounds__(256) void prepass(const float* __restrict__ X,
                                               const float* __restrict__ Wq,
                                               const float* __restrict__ Wk,
                                               const float* __restrict__ Wv,
                                               const float* __restrict__ Wu) {
  __shared__ float tile[32 * 33];
  int bid = blockIdx.x;
  if (bid < 512) {                      // split X
    int e4 = bid * 256 + threadIdx.x;
    float4 v = *(const float4*)(X + e4 * 4);
    float f[4] = {v.x, v.y, v.z, v.w};
    __nv_bfloat16 h[4], l[4];
#pragma unroll
    for (int i = 0; i < 4; i++) {
      h[i] = __float2bfloat16(f[i]);
      l[i] = __float2bfloat16(f[i] - __bfloat162float(h[i]));
    }
    *(uint2*)&g_Xh[e4 * 4] = *(uint2*)h;
    *(uint2*)&g_Xl[e4 * 4] = *(uint2*)l;
  } else {
    int r = bid - 512;                  // 0..511
    int which = r >> 7, sub = r & 127;
    if (which < 3) {                    // Wq/Wk/Wv
      const float* src = (which == 0) ? Wq : ((which == 1) ? Wk : Wv);
      twsplit_body(src, g_Wth, g_Wtl, 1024, 128, which * 1024,
                   sub & 31, sub >> 5, tile);
    } else {                            // Wu
      twsplit_body(Wu, g_Wuth, g_Wutl, 128, 1024, 0,
                   sub & 3, sub >> 2, tile);
    }
  }
}

// ---------------- Kernel 1: fused QKV projection (tensor core) -------------
__global__ __launch_bounds__(256) void qkv_gemm() {
  __shared__ __nv_bfloat16 sAh[128 * SPAD], sAl[128 * SPAD];
  __shared__ __nv_bfloat16 sBh[128 * SPAD], sBl[128 * SPAD];
  int bn = blockIdx.x, bm = blockIdx.y;
  int n_glob0 = bn * 128;
  int tid = threadIdx.x, wid = tid >> 5, lane = tid & 31;
  int wm = wid >> 1, wn = wid & 1;
  float acc[2][8][4] = {};

  for (int kc = 0; kc < 128; kc += 32) {
#pragma unroll
    for (int it = 0; it < 2; it++) {
      int idx = tid + it * 256;             // 0..511
      int r = idx >> 2, c = idx & 3;
      int so = r * SPAD + c * 8;
      size_t ga = (size_t)(bm * 128 + r) * 128 + kc + c * 8;
      size_t gb = (size_t)(n_glob0 + r) * 128 + kc + c * 8;
      *(uint4*)&sAh[so] = *(const uint4*)&g_Xh[ga];
      *(uint4*)&sAl[so] = *(const uint4*)&g_Xl[ga];
      *(uint4*)&sBh[so] = *(const uint4*)&g_Wth[gb];
      *(uint4*)&sBl[so] = *(const uint4*)&g_Wtl[gb];
    }
    __syncthreads();
#pragma unroll
    for (int ks = 0; ks < 32; ks += 16) {
      uint32_t Ah[2][4], Al[2][4], Bh[4][4], Bl[4][4];
#pragma unroll
      for (int mt = 0; mt < 2; mt++) {
        int off = (wm * 32 + mt * 16 + (lane & 15)) * SPAD + ks + 8 * (lane >> 4);
        ldsm4(Ah[mt], &sAh[off]);
        ldsm4(Al[mt], &sAl[off]);
      }
#pragma unroll
      for (int nb = 0; nb < 4; nb++) {
        int off = (wn * 64 + nb * 16 + 8 * ((lane >> 4) & 1) + (lane & 7)) * SPAD
                  + ks + 8 * ((lane >> 3) & 1);
        ldsm4(Bh[nb], &sBh[off]);
        ldsm4(Bl[nb], &sBl[off]);
      }
#pragma unroll
      for (int mt = 0; mt < 2; mt++)
#pragma unroll
        for (int nb = 0; nb < 4; nb++) {
          mma16816(acc[mt][nb * 2],     Ah[mt], &Bh[nb][0]);
          mma16816(acc[mt][nb * 2],     Ah[mt], &Bl[nb][0]);
          mma16816(acc[mt][nb * 2],     Al[mt], &Bh[nb][0]);
          mma16816(acc[mt][nb * 2 + 1], Ah[mt], &Bh[nb][2]);
          mma16816(acc[mt][nb * 2 + 1], Ah[mt], &Bl[nb][2]);
          mma16816(acc[mt][nb * 2 + 1], Al[mt], &Bh[nb][2]);
        }
    }
    __syncthreads();
  }

  int g = lane >> 2, t = lane & 3;
  int seg = n_glob0 >> 10;                          // 0=Q 1=K 2=V
  float scale = (seg < 2) ? 0.29730177875068026f : 1.0f; // 1/128^0.25
#pragma unroll
  for (int mt = 0; mt < 2; mt++)
#pragma unroll
    for (int nt = 0; nt < 8; nt++) {
      int row = bm * 128 + wm * 32 + mt * 16 + g;
      int col = n_glob0 + wn * 64 + nt * 8 + 2 * t;
      float2 v0 = make_float2(acc[mt][nt][0] * scale, acc[mt][nt][1] * scale);
      float2 v1 = make_float2(acc[mt][nt][2] * scale, acc[mt][nt][3] * scale);
      if (seg == 0) {
        *(float2*)&g_q[(size_t)row * D1 + col] = v0;
        *(float2*)&g_q[(size_t)(row + 8) * D1 + col] = v1;
      } else {
        int c = col & 1023, h = c >> 7, d = c & 127;
        int b = row >> 11, tt = row & 2047;
        __half* dst = (seg == 1) ? g_K : g_V;
        size_t base = ((size_t)(b * NH + h) * Tn + tt) * EMB + d;
        *(__half2*)&dst[base] = __float22half2_rn(v0);
        *(__half2*)&dst[base + 8 * EMB] = __float22half2_rn(v1);
      }
    }
}

// ---------------- Kernel 2: indices + weights (2 tokens / 128-thr block) ---
__global__ __launch_bounds__(128) void idxw_kernel(const float* __restrict__ sp,
                                                   const float* __restrict__ mvals) {
  int sub = threadIdx.x >> 6;          // 0/1
  int p = threadIdx.x & 63;
  int token = blockIdx.x * 2 + sub;    // 0..4095
  int b = token >> 11, t = token & 2047;
  __shared__ float s_mean[2][Mv];
  __shared__ float s_sigma_inv;
  __shared__ int   s_idx[2][Pp];
  __shared__ float s_ptsfl[2][Pp];
  __shared__ float s_dens[2][Pp][Mv];
  __shared__ float s_colinv[2][Mv];

  float dil = sp[0];
  if (p < Mv) {
    float off = __fmul_rn((float)(p - 4), dil);
    float mu  = __fadd_rn((float)t, off);
    mu = fminf(fmaxf(mu, 0.0f), (float)(Tn - 1));
    s_mean[sub][p] = mu;
  }
  if (threadIdx.x == 0) {
    float s = sp[1] + 2.0f;                 // SIGMA_BOOST
    float sigma = log1pf(expf(s)) + 1e-7f;  // softplus + EPS
    s_sigma_inv = 1.0f / sigma;
  }
  __syncthreads();

  if (p < Pp) {
    int m = p >> 2, slot = p & 3;
    float fl = floorf(s_mean[sub][m]);
    float val;
    if (slot == 0) val = fl;
    else if (slot == 1) val = fl + 1.0f;
    else {
      // JAX partitionable threefry (verified in R2)
      uint32_t k2a = 0u, k2b = 1u;
      tf2x32(0u, 42u, k2a, k2b);
      uint32_t i = (uint32_t)(b * 36864 + t * 18 + m * 2 + (slot - 2));
      uint32_t x0 = 0u, x1 = i;
      tf2x32(k2a, k2b, x0, x1);
      uint32_t bits = x0 ^ x1;
      val = (float)(bits & 2047u);
    }
    val = fminf(fmaxf(val, 0.0f), (float)(Tn - 1));
    int iv = (int)val;
    s_idx[sub][p] = iv;
    s_ptsfl[sub][p] = (float)iv;
  }
  __syncthreads();

  if (p < Pp) {
    bool dup = false;
    int my = s_idx[sub][p];
    for (int q = 0; q < p; q++) dup |= (s_idx[sub][q] == my);
    float inv_s = s_sigma_inv;
#pragma unroll
    for (int m = 0; m < Mv; m++) {
      float d = (s_ptsfl[sub][p] - s_mean[sub][m]) * inv_s;
      s_dens[sub][p][m] = dup ? 0.0f : expf(-0.5f * d * d);
    }
  }
  __syncthreads();

  if (p < Mv) {
    float sum = 0.0f;
    for (int q = 0; q < Pp; q++) sum += s_dens[sub][q][p];
    s_colinv[sub][p] = 1.0f / sum;
  }
  __syncthreads();

  if (p < Pp) {
    float w = 0.0f;
#pragma unroll
    for (int m = 0; m < Mv; m++) w += s_dens[sub][p][m] * s_colinv[sub][m] * mvals[m];
    g_idx[token * Pp + p] = s_idx[sub][p];
    g_w[token * Pp + p] = w;
  }
}

// ---------------- Kernel 3: gathered attention (group-parallel points) -----
// Warp = (token, head). QK: 8-lane groups x 4 points/iter (3-shfl reduce).
// Softmax: one exp per point across lanes, 1/sum folded into probs.
// V: 16-lane halves x 2 points/iter, uint4 loads, 8-wide final reduce.
__global__ __launch_bounds__(512) void attn_kernel() {
  __shared__ float s_logit[16][Pp];
  __shared__ float s_a[16][Pp];
  int tid = threadIdx.x;
  int wid = tid >> 5, lane = tid & 31;
  int g = lane >> 3, sub = lane & 7;       // QK: 4 groups x 8 lanes
  int half16 = lane >> 4, s16 = lane & 15; // V: 2 halves x 16 lanes
  int token = blockIdx.x * 16 + wid;
  int h = blockIdx.y;
  int b = token >> 11;

  const float* qp = g_q + (size_t)token * D1 + h * EMB;
  const int*   ip = g_idx + token * Pp;
  const float* wp = g_w + token * Pp;
  const __half* kb = g_K + (size_t)(b * NH + h) * Tn * EMB;
  const __half* vb = g_V + (size_t)(b * NH + h) * Tn * EMB;

  // preload q dims for this lane's two 8-dim chunks
  float q0[8], q1[8];
  *(float4*)&q0[0] = *(const float4*)&qp[sub * 8];
  *(float4*)&q0[4] = *(const float4*)&qp[sub * 8 + 4];
  *(float4*)&q1[0] = *(const float4*)&qp[64 + sub * 8];
  *(float4*)&q1[4] = *(const float4*)&qp[64 + sub * 8 + 4];

  // ---- QK logits: 9 iterations x 4 points ----
#pragma unroll
  for (int it = 0; it < 9; it++) {
    int p = it * 4 + g;
    int j = ip[p];                               // LDG broadcast (4 addrs)
    const __half* kr = kb + (size_t)j * EMB;
    uint4 k0 = *(const uint4*)&kr[sub * 8];
    uint4 k1 = *(const uint4*)&kr[64 + sub * 8];
    float d = dot8(q0, k0) + dot8(q1, k1);
    d += __shfl_xor_sync(0xffffffffu, d, 4);
    d += __shfl_xor_sync(0xffffffffu, d, 2);
    d += __shfl_xor_sync(0xffffffffu, d, 1);
    if (sub == 0) s_logit[wid][p] = wp[p] * d;
  }
  __syncwarp();

  // ---- softmax probs (one exp per point), 1/sum folded in ----
  float l0 = s_logit[wid][lane];
  float l1 = (lane < 4) ? s_logit[wid][32 + lane] : -1e30f;
  float mx = fmaxf(l0, l1);
#pragma unroll
  for (int o = 16; o >= 1; o >>= 1)
    mx = fmaxf(mx, __shfl_xor_sync(0xffffffffu, mx, o));
  float a0 = __expf(l0 - mx);
  float a1 = (lane < 4) ? __expf(l1 - mx) : 0.0f;
  float sm = a0 + a1;
#pragma unroll
  for (int o = 16; o >= 1; o >>= 1)
    sm += __shfl_xor_sync(0xffffffffu, sm, o);
  float inv = 1.0f / sm;
  s_a[wid][lane] = a0 * inv;
  if (lane < 4) s_a[wid][32 + lane] = a1 * inv;
  __syncwarp();

  // ---- V accumulation: 18 iterations x 2 points, lane owns 8 dims ----
  float vacc[8] = {};
#pragma unroll
  for (int it = 0; it < 18; it++) {
    int p = it * 2 + half16;
    int j = ip[p];                               // LDG broadcast (2 addrs)
    float a = s_a[wid][p];
    uint4 v = *(const uint4*)&vb[(size_t)j * EMB + s16 * 8];
    float2 f0 = __half22float2(*(__half2*)&v.x);
    float2 f1 = __half22float2(*(__half2*)&v.y);
    float2 f2 = __half22float2(*(__half2*)&v.z);
    float2 f3 = __half22float2(*(__half2*)&v.w);
    vacc[0] += a * f0.x; vacc[1] += a * f0.y;
    vacc[2] += a * f1.x; vacc[3] += a * f1.y;
    vacc[4] += a * f2.x; vacc[5] += a * f2.y;
    vacc[6] += a * f3.x; vacc[7] += a * f3.y;
  }
  // combine halves (same dims, different point subsets)
#pragma unroll
  for (int d = 0; d < 8; d++)
    vacc[d] += __shfl_xor_sync(0xffffffffu, vacc[d], 16);

  if (half16 == 0) {
    __nv_bfloat16 hh[8], ll[8];
#pragma unroll
    for (int i = 0; i < 8; i++) {
      hh[i] = __float2bfloat16(vacc[i]);
      ll[i] = __float2bfloat16(vacc[i] - __bfloat162float(hh[i]));
    }
    size_t base = (size_t)token * D1 + h * EMB + s16 * 8;
    *(uint4*)&g_aoh[base] = *(uint4*)hh;
    *(uint4*)&g_aol[base] = *(uint4*)ll;
  }
}

// ---------------- Kernel 4: output GEMM (tensor core, split-K x4) -----------
__global__ __launch_bounds__(256) void out_gemm() {
  __shared__ __nv_bfloat16 sAh[128 * SPAD], sAl[128 * SPAD];
  __shared__ __nv_bfloat16 sBh[128 * SPAD], sBl[128 * SPAD];
  int bm = blockIdx.x, kslice = blockIdx.y;
  int tid = threadIdx.x, wid = tid >> 5, lane = tid & 31;
  int wm = wid >> 1, wn = wid & 1;
  float acc[2][8][4] = {};
  int kbase = kslice * 256;

  for (int kc = kbase; kc < kbase + 256; kc += 32) {
#pragma unroll
    for (int it = 0; it < 2; it++) {
      int idx = tid + it * 256;
      int r = idx >> 2, c = idx & 3;
      int so = r * SPAD + c * 8;
      size_t ga = (size_t)(bm * 128 + r) * D1 + kc + c * 8;
      size_t gb = (size_t)r * D1 + kc + c * 8;   // Wu^T rows = n (128)
      *(uint4*)&sAh[so] = *(const uint4*)&g_aoh[ga];
      *(uint4*)&sAl[so] = *(const uint4*)&g_aol[ga];
      *(uint4*)&sBh[so] = *(const uint4*)&g_Wuth[gb];
      *(uint4*)&sBl[so] = *(const uint4*)&g_Wutl[gb];
    }
    __syncthreads();
#pragma unroll
    for (int ks = 0; ks < 32; ks += 16) {
      uint32_t Ah[2][4], Al[2][4], Bh[4][4], Bl[4][4];
#pragma unroll
      for (int mt = 0; mt < 2; mt++) {
        int off = (wm * 32 + mt * 16 + (lane & 15)) * SPAD + ks + 8 * (lane >> 4);
        ldsm4(Ah[mt], &sAh[off]);
        ldsm4(Al[mt], &sAl[off]);
      }
#pragma unroll
      for (int nb = 0; nb < 4; nb++) {
        int off = (wn * 64 + nb * 16 + 8 * ((lane >> 4) & 1) + (lane & 7)) * SPAD
                  + ks + 8 * ((lane >> 3) & 1);
        ldsm4(Bh[nb], &sBh[off]);
        ldsm4(Bl[nb], &sBl[off]);
      }
#pragma unroll
      for (int mt = 0; mt < 2; mt++)
#pragma unroll
        for (int nb = 0; nb < 4; nb++) {
          mma16816(acc[mt][nb * 2],     Ah[mt], &Bh[nb][0]);
          mma16816(acc[mt][nb * 2],     Ah[mt], &Bl[nb][0]);
          mma16816(acc[mt][nb * 2],     Al[mt], &Bh[nb][0]);
          mma16816(acc[mt][nb * 2 + 1], Ah[mt], &Bh[nb][2]);
          mma16816(acc[mt][nb * 2 + 1], Ah[mt], &Bl[nb][2]);
          mma16816(acc[mt][nb * 2 + 1], Al[mt], &Bh[nb][2]);
        }
    }
    __syncthreads();
  }

  int g = lane >> 2, t = lane & 3;
  float* dst = g_part[kslice];
#pragma unroll
  for (int mt = 0; mt < 2; mt++)
#pragma unroll
    for (int nt = 0; nt < 8; nt++) {
      int row = bm * 128 + wm * 32 + mt * 16 + g;
      int col = wn * 64 + nt * 8 + 2 * t;
      *(float2*)&dst[(size_t)row * 128 + col] =
          make_float2(acc[mt][nt][0], acc[mt][nt][1]);
      *(float2*)&dst[(size_t)(row + 8) * 128 + col] =
          make_float2(acc[mt][nt][2], acc[mt][nt][3]);
    }
}

// Deterministic reduce of the 4 split-K partials + bias.
__global__ __launch_bounds__(256) void out_reduce(float* __restrict__ Cout,
                                                  const float* __restrict__ bu) {
  int e4 = blockIdx.x * 256 + threadIdx.x;   // float4 index, 0..131071
  int col0 = (e4 * 4) & 127;
  float4 s = *(const float4*)(bu + col0);
#pragma unroll
  for (int ks = 0; ks < 4; ks++) {
    float4 p = *(const float4*)(g_part[ks] + e4 * 4);
    s.x += p.x; s.y += p.y; s.z += p.z; s.w += p.w;
  }
  *(float4*)(Cout + e4 * 4) = s;
}

// ---------------- launch ----------------------------------------------------
extern "C" void kernel_launch(void* const* d_in, const int* in_sizes, int n_in,
                              void* d_out, int out_size) {
  const float* x   = (const float*)d_in[0];
  const float* sp  = (const float*)d_in[1];
  const float* mv  = (const float*)d_in[2];
  const float* Wq  = (const float*)d_in[3];
  const float* Wk  = (const float*)d_in[4];
  const float* Wv  = (const float*)d_in[5];
  const float* Wu  = (const float*)d_in[6];
  const float* bu  = (const float*)d_in[7];
  float* out = (float*)d_out;

  prepass<<<1024, 256>>>(x, Wq, Wk, Wv, Wu);
  idxw_kernel<<<2048, 128>>>(sp, mv);
  qkv_gemm<<<dim3(24, 32), 256>>>();
  attn_kernel<<<dim3(256, 8), 512>>>();
  out_gemm<<<dim3(32, 4), 256>>>();
  out_reduce<<<512, 256>>>(out, bu);
}